// round 2
// baseline (speedup 1.0000x reference)
#include <cuda_runtime.h>
#include <math.h>

// ---------------- problem constants ----------------
#define BB   4
#define SS   2048
#define DD   1024
#define HH   16
#define DH   64
#define DFF  4096
#define MTOT (BB*SS)   // 8192 rows

// ---------------- scratch (device globals; no allocations allowed) ----------
__device__ float g_y  [MTOT*DD];
__device__ float g_q  [MTOT*DD];
__device__ float g_k  [MTOT*DD];
__device__ float g_v  [MTOT*DD];
__device__ float g_ctx[MTOT*DD];
__device__ float g_x1 [MTOT*DD];
__device__ float g_y2 [MTOT*DD];
__device__ float g_h  [MTOT*DFF];

// ---------------- packed f32x2 helpers (Blackwell) ----------------
__device__ __forceinline__ unsigned long long pack2(float x) {
    unsigned long long p; unsigned xi = __float_as_uint(x);
    asm("mov.b64 %0, {%1, %1};" : "=l"(p) : "r"(xi));
    return p;
}
__device__ __forceinline__ void fma2(unsigned long long& d,
                                     unsigned long long a,
                                     unsigned long long b) {
    asm("fma.rn.f32x2 %0, %1, %2, %0;" : "+l"(d) : "l"(a), "l"(b));
}
__device__ __forceinline__ float2 unpack2(unsigned long long p) {
    float2 r;
    asm("mov.b64 {%0, %1}, %2;" : "=f"(r.x), "=f"(r.y) : "l"(p));
    return r;
}

// ---------------- LayerNorm: one block per row of 1024 ----------------
__global__ __launch_bounds__(256)
void ln_kernel(const float* __restrict__ x,
               const float* __restrict__ alpha,
               const float* __restrict__ beta,
               float* __restrict__ y)
{
    int row = blockIdx.x;
    int t = threadIdx.x;
    const float4* xr = (const float4*)(x + (size_t)row * DD);
    float4 v = xr[t];
    float s  = v.x + v.y + v.z + v.w;
    float sq = v.x*v.x + v.y*v.y + v.z*v.z + v.w*v.w;
    #pragma unroll
    for (int o = 16; o; o >>= 1) {
        s  += __shfl_xor_sync(0xffffffffu, s,  o);
        sq += __shfl_xor_sync(0xffffffffu, sq, o);
    }
    __shared__ float red[2][8];
    int w = t >> 5, lane = t & 31;
    if (lane == 0) { red[0][w] = s; red[1][w] = sq; }
    __syncthreads();
    if (t == 0) {
        float S = 0.f, Q = 0.f;
        #pragma unroll
        for (int i = 0; i < 8; i++) { S += red[0][i]; Q += red[1][i]; }
        float mean = S * (1.0f / DD);
        float var  = Q * (1.0f / DD) - mean * mean;
        red[0][0] = mean;
        red[1][0] = rsqrtf(var + 1e-5f);
    }
    __syncthreads();
    float mean = red[0][0], rstd = red[1][0];
    float4 a = ((const float4*)alpha)[t];
    float4 b = ((const float4*)beta)[t];
    float4 o;
    o.x = a.x * (v.x - mean) * rstd + b.x;
    o.y = a.y * (v.y - mean) * rstd + b.y;
    o.z = a.z * (v.z - mean) * rstd + b.z;
    o.w = a.w * (v.w - mean) * rstd + b.w;
    ((float4*)(y + (size_t)row * DD))[t] = o;
}

// ---------------- SGEMM 128x128x8 with packed f32x2 FMA ----------------
// EPI: 0 = C = A@B
//      1 = C = res + A@B
//      2 = C = gelu(A@B + bias)
//      3 = C = res + A@B + bias
__device__ __forceinline__ float gelu_exact(float v) {
    return 0.5f * v * (1.0f + erff(v * 0.70710678118654752f));
}

template<int EPI>
__global__ __launch_bounds__(256)
void gemm_kernel(const float* __restrict__ A, const float* __restrict__ B,
                 const float* __restrict__ bias, const float* __restrict__ res,
                 float* __restrict__ C, int M, int N, int K)
{
    __shared__ __align__(16) float As[8][128];
    __shared__ __align__(16) float Bs[8][128];

    int tid = threadIdx.x;
    int m0 = blockIdx.y * 128, n0 = blockIdx.x * 128;
    int ar = tid >> 1, ac = (tid & 1) * 4;     // A tile loader: 128 rows x 8 cols
    int br = tid >> 5, bc = (tid & 31) * 4;    // B tile loader: 8 rows x 128 cols
    const float* Ap = A + (size_t)(m0 + ar) * K + ac;
    const float* Bp = B + (size_t)br * N + n0 + bc;
    int ty = tid >> 4, tx = tid & 15;          // 16x16 thread grid, 8x8 microtile

    unsigned long long acc[8][4];
    #pragma unroll
    for (int i = 0; i < 8; i++)
        #pragma unroll
        for (int j = 0; j < 4; j++) acc[i][j] = 0ull;

    for (int k0 = 0; k0 < K; k0 += 8) {
        float4 av = *(const float4*)Ap; Ap += 8;
        float4 bv = *(const float4*)Bp; Bp += (size_t)8 * N;
        As[ac + 0][ar] = av.x; As[ac + 1][ar] = av.y;
        As[ac + 2][ar] = av.z; As[ac + 3][ar] = av.w;
        *(float4*)&Bs[br][bc] = bv;
        __syncthreads();
        #pragma unroll
        for (int k = 0; k < 8; k++) {
            float4 a0 = *(const float4*)&As[k][ty * 8];
            float4 a1 = *(const float4*)&As[k][ty * 8 + 4];
            ulonglong2 b01 = *(const ulonglong2*)&Bs[k][tx * 8];
            ulonglong2 b23 = *(const ulonglong2*)&Bs[k][tx * 8 + 4];
            unsigned long long ap[8] = {
                pack2(a0.x), pack2(a0.y), pack2(a0.z), pack2(a0.w),
                pack2(a1.x), pack2(a1.y), pack2(a1.z), pack2(a1.w)};
            unsigned long long bp[4] = { b01.x, b01.y, b23.x, b23.y };
            #pragma unroll
            for (int i = 0; i < 8; i++) {
                fma2(acc[i][0], ap[i], bp[0]);
                fma2(acc[i][1], ap[i], bp[1]);
                fma2(acc[i][2], ap[i], bp[2]);
                fma2(acc[i][3], ap[i], bp[3]);
            }
        }
        __syncthreads();
    }

    // epilogue
    #pragma unroll
    for (int i = 0; i < 8; i++) {
        int grow = m0 + ty * 8 + i;
        int gcol0 = n0 + tx * 8;
        float out[8];
        #pragma unroll
        for (int j = 0; j < 4; j++) {
            float2 u = unpack2(acc[i][j]);
            out[2 * j] = u.x; out[2 * j + 1] = u.y;
        }
        if (EPI == 2 || EPI == 3) {
            const float4* bp2 = (const float4*)(bias + gcol0);
            float4 b0 = bp2[0], b1 = bp2[1];
            out[0] += b0.x; out[1] += b0.y; out[2] += b0.z; out[3] += b0.w;
            out[4] += b1.x; out[5] += b1.y; out[6] += b1.z; out[7] += b1.w;
        }
        if (EPI == 2) {
            #pragma unroll
            for (int j = 0; j < 8; j++) out[j] = gelu_exact(out[j]);
        }
        if (EPI == 1 || EPI == 3) {
            const float4* rp = (const float4*)(res + (size_t)grow * N + gcol0);
            float4 r0 = rp[0], r1 = rp[1];
            out[0] += r0.x; out[1] += r0.y; out[2] += r0.z; out[3] += r0.w;
            out[4] += r1.x; out[5] += r1.y; out[6] += r1.z; out[7] += r1.w;
        }
        float4 o0 = make_float4(out[0], out[1], out[2], out[3]);
        float4 o1 = make_float4(out[4], out[5], out[6], out[7]);
        float4* cp = (float4*)(C + (size_t)grow * N + gcol0);
        cp[0] = o0; cp[1] = o1;
    }
}

// ---------------- Flash attention, fp32, BQ=BK=64, dh=64 ----------------
#define BQ  64
#define BKT 64
#define ATTN_SMEM (4 * BQ * DH * (int)sizeof(float) + BKT * (int)sizeof(int))

__global__ __launch_bounds__(256)
void attn_kernel(const float* __restrict__ Qg, const float* __restrict__ Kg,
                 const float* __restrict__ Vg, const int* __restrict__ amask,
                 float* __restrict__ ctx)
{
    extern __shared__ __align__(16) float sh[];
    float* Qs  = sh;                    // [BQ][DH]
    float* KsT = Qs  + BQ * DH;         // [DH][BKT]  (transposed)
    float* Vs  = KsT + DH * BKT;        // [BKT][DH]
    float* Ps  = Vs  + BKT * DH;        // [BQ][BKT]
    int*   mks = (int*)(Ps + BQ * BKT); // [BKT]

    int tid = threadIdx.x;
    int qt = blockIdx.x, h = blockIdx.y, b = blockIdx.z;
    int q0 = qt * BQ;
    int ty = tid >> 4, tx = tid & 15;

    // load Q tile: rows q0..q0+63, cols h*64..h*64+63
    {
        int r = tid >> 2; int c0 = (tid & 3) * 16;
        const float4* src = (const float4*)(Qg + ((size_t)(b * SS + q0 + r)) * DD + h * DH + c0);
        float4* dst = (float4*)(Qs + r * DH + c0);
        dst[0] = src[0]; dst[1] = src[1]; dst[2] = src[2]; dst[3] = src[3];
    }

    int mq[4];
    #pragma unroll
    for (int i = 0; i < 4; i++) mq[i] = amask[b * SS + q0 + ty * 4 + i];

    float m[4], l[4], o[4][4];
    #pragma unroll
    for (int i = 0; i < 4; i++) {
        m[i] = -1e30f; l[i] = 0.0f;
        #pragma unroll
        for (int j = 0; j < 4; j++) o[i][j] = 0.0f;
    }

    int ntiles = qt + 1;   // causal: only tiles with k0 <= q_max
    for (int t = 0; t < ntiles; t++) {
        int k0 = t * BKT;
        __syncthreads();   // protect Ks/Vs/Ps from previous iteration (and Q load, iter 0)
        {
            int r = tid >> 2; int c0 = (tid & 3) * 16;
            const float* ksrc = Kg + ((size_t)(b * SS + k0 + r)) * DD + h * DH;
            #pragma unroll
            for (int c = 0; c < 16; c += 4) {
                float4 kv = *(const float4*)(ksrc + c0 + c);
                KsT[(c0 + c + 0) * BKT + r] = kv.x;
                KsT[(c0 + c + 1) * BKT + r] = kv.y;
                KsT[(c0 + c + 2) * BKT + r] = kv.z;
                KsT[(c0 + c + 3) * BKT + r] = kv.w;
            }
            const float4* vsrc = (const float4*)(Vg + ((size_t)(b * SS + k0 + r)) * DD + h * DH + c0);
            float4* vdst = (float4*)(Vs + r * DH + c0);
            vdst[0] = vsrc[0]; vdst[1] = vsrc[1]; vdst[2] = vsrc[2]; vdst[3] = vsrc[3];
            if (tid < BKT) mks[tid] = amask[b * SS + k0 + tid];
        }
        __syncthreads();

        // S = Q @ K^T   (4x4 per thread)
        float s[4][4];
        #pragma unroll
        for (int i = 0; i < 4; i++)
            #pragma unroll
            for (int j = 0; j < 4; j++) s[i][j] = 0.0f;

        #pragma unroll 4
        for (int d = 0; d < DH; d += 4) {
            float4 q4[4], k4[4];
            #pragma unroll
            for (int i = 0; i < 4; i++)  q4[i]  = *(const float4*)&Qs[(ty * 4 + i) * DH + d];
            #pragma unroll
            for (int dd = 0; dd < 4; dd++) k4[dd] = *(const float4*)&KsT[(d + dd) * BKT + tx * 4];
            #pragma unroll
            for (int i = 0; i < 4; i++) {
                s[i][0] += q4[i].x * k4[0].x + q4[i].y * k4[1].x + q4[i].z * k4[2].x + q4[i].w * k4[3].x;
                s[i][1] += q4[i].x * k4[0].y + q4[i].y * k4[1].y + q4[i].z * k4[2].y + q4[i].w * k4[3].y;
                s[i][2] += q4[i].x * k4[0].z + q4[i].y * k4[1].z + q4[i].z * k4[2].z + q4[i].w * k4[3].z;
                s[i][3] += q4[i].x * k4[0].w + q4[i].y * k4[1].w + q4[i].z * k4[2].w + q4[i].w * k4[3].w;
            }
        }

        // scale + mask, online softmax
        const float scale = 0.125f;  // 1/sqrt(64)
        #pragma unroll
        for (int i = 0; i < 4; i++) {
            int qg = q0 + ty * 4 + i;
            #pragma unroll
            for (int j = 0; j < 4; j++) {
                int kloc = tx * 4 + j;
                int kg = k0 + kloc;
                float v = s[i][j] * scale;
                if (kg > qg || mks[kloc] == 0 || mq[i] == 0) v = -1e30f;
                s[i][j] = v;
            }
            float mt = fmaxf(fmaxf(s[i][0], s[i][1]), fmaxf(s[i][2], s[i][3]));
            #pragma unroll
            for (int off = 8; off; off >>= 1)
                mt = fmaxf(mt, __shfl_xor_sync(0xffffffffu, mt, off));
            float mn = fmaxf(m[i], mt);
            float corr = __expf(m[i] - mn);
            m[i] = mn;
            float rs = 0.0f;
            #pragma unroll
            for (int j = 0; j < 4; j++) {
                float p = __expf(s[i][j] - mn);
                s[i][j] = p; rs += p;
            }
            #pragma unroll
            for (int off = 8; off; off >>= 1)
                rs += __shfl_xor_sync(0xffffffffu, rs, off);
            l[i] = l[i] * corr + rs;
            #pragma unroll
            for (int j = 0; j < 4; j++) o[i][j] *= corr;
            *(float4*)&Ps[(ty * 4 + i) * BKT + tx * 4] =
                make_float4(s[i][0], s[i][1], s[i][2], s[i][3]);
        }
        __syncthreads();

        // O += P @ V
        #pragma unroll 4
        for (int k = 0; k < BKT; k += 4) {
            float4 p4[4], v4[4];
            #pragma unroll
            for (int i = 0; i < 4; i++)  p4[i]  = *(const float4*)&Ps[(ty * 4 + i) * BKT + k];
            #pragma unroll
            for (int kk = 0; kk < 4; kk++) v4[kk] = *(const float4*)&Vs[(k + kk) * DH + tx * 4];
            #pragma unroll
            for (int i = 0; i < 4; i++) {
                o[i][0] += p4[i].x * v4[0].x + p4[i].y * v4[1].x + p4[i].z * v4[2].x + p4[i].w * v4[3].x;
                o[i][1] += p4[i].x * v4[0].y + p4[i].y * v4[1].y + p4[i].z * v4[2].y + p4[i].w * v4[3].y;
                o[i][2] += p4[i].x * v4[0].z + p4[i].y * v4[1].z + p4[i].z * v4[2].z + p4[i].w * v4[3].z;
                o[i][3] += p4[i].x * v4[0].w + p4[i].y * v4[1].w + p4[i].z * v4[2].w + p4[i].w * v4[3].w;
            }
        }
    }

    // write ctx (layout [B,S,H,dh] flattened into [B*S, D])
    #pragma unroll
    for (int i = 0; i < 4; i++) {
        float inv = 1.0f / l[i];
        float4 ov = make_float4(o[i][0] * inv, o[i][1] * inv, o[i][2] * inv, o[i][3] * inv);
        *(float4*)(ctx + ((size_t)(b * SS + q0 + ty * 4 + i)) * DD + h * DH + tx * 4) = ov;
    }
}

// ---------------- orchestration ----------------
extern "C" void kernel_launch(void* const* d_in, const int* in_sizes, int n_in,
                              void* d_out, int out_size)
{
    const float* x    = (const float*)d_in[0];
    const int*   am   = (const int*)  d_in[1];
    const float* ln1a = (const float*)d_in[2];
    const float* ln1b = (const float*)d_in[3];
    const float* ln2a = (const float*)d_in[4];
    const float* ln2b = (const float*)d_in[5];
    const float* Wq   = (const float*)d_in[6];
    const float* Wk   = (const float*)d_in[7];
    const float* Wv   = (const float*)d_in[8];
    const float* Wo   = (const float*)d_in[9];
    const float* W1   = (const float*)d_in[10];
    const float* b1   = (const float*)d_in[11];
    const float* W2   = (const float*)d_in[12];
    const float* b2   = (const float*)d_in[13];
    float* out = (float*)d_out;

    float *y, *q, *k, *v, *ctx, *x1, *y2, *hbuf;
    cudaGetSymbolAddress((void**)&y,    g_y);
    cudaGetSymbolAddress((void**)&q,    g_q);
    cudaGetSymbolAddress((void**)&k,    g_k);
    cudaGetSymbolAddress((void**)&v,    g_v);
    cudaGetSymbolAddress((void**)&ctx,  g_ctx);
    cudaGetSymbolAddress((void**)&x1,   g_x1);
    cudaGetSymbolAddress((void**)&y2,   g_y2);
    cudaGetSymbolAddress((void**)&hbuf, g_h);

    cudaFuncSetAttribute(attn_kernel,
                         cudaFuncAttributeMaxDynamicSharedMemorySize, ATTN_SMEM);

    dim3 gD(DD / 128, MTOT / 128);    // (8, 64)
    dim3 gF(DFF / 128, MTOT / 128);   // (32, 64)

    // LN1
    ln_kernel<<<MTOT, 256>>>(x, ln1a, ln1b, y);
    // Q, K, V projections
    gemm_kernel<0><<<gD, 256>>>(y, Wq, nullptr, nullptr, q, MTOT, DD, DD);
    gemm_kernel<0><<<gD, 256>>>(y, Wk, nullptr, nullptr, k, MTOT, DD, DD);
    gemm_kernel<0><<<gD, 256>>>(y, Wv, nullptr, nullptr, v, MTOT, DD, DD);
    // attention
    attn_kernel<<<dim3(SS / BQ, HH, BB), 256, ATTN_SMEM>>>(q, k, v, am, ctx);
    // output projection + residual
    gemm_kernel<1><<<gD, 256>>>(ctx, Wo, nullptr, x, x1, MTOT, DD, DD);
    // LN2
    ln_kernel<<<MTOT, 256>>>(x1, ln2a, ln2b, y2);
    // FFN up + GELU
    gemm_kernel<2><<<gF, 256>>>(y2, W1, b1, nullptr, hbuf, MTOT, DFF, DD);
    // FFN down + bias + residual -> output
    gemm_kernel<3><<<gD, 256>>>(hbuf, W2, b2, x1, out, MTOT, DD, DFF);
}

// round 8
// speedup vs baseline: 1.9266x; 1.9266x over previous
#include <cuda_runtime.h>
#include <cuda_bf16.h>
#include <cstdint>
#include <math.h>

// ---------------- problem constants ----------------
#define BB   4
#define SS   2048
#define DD   1024
#define HH   16
#define DH   64
#define DFF  4096
#define MTOT (BB*SS)   // 8192 rows

// ---------------- scratch (device globals; no allocations allowed) ----------
__device__ float g_q [MTOT*DD];
__device__ float g_k [MTOT*DD];
__device__ float g_v [MTOT*DD];
__device__ float g_x1[MTOT*DD];

__device__ unsigned short g_yh [MTOT*DD],  g_yl [MTOT*DD];
__device__ unsigned short g_ch [MTOT*DD],  g_cl [MTOT*DD];
__device__ unsigned short g_y2h[MTOT*DD],  g_y2l[MTOT*DD];
__device__ unsigned short g_hh [MTOT*DFF], g_hl [MTOT*DFF];

__device__ unsigned short g_wqh[DD*DD],  g_wql[DD*DD];
__device__ unsigned short g_wkh[DD*DD],  g_wkl[DD*DD];
__device__ unsigned short g_wvh[DD*DD],  g_wvl[DD*DD];
__device__ unsigned short g_woh[DD*DD],  g_wol[DD*DD];
__device__ unsigned short g_w1h[DD*DFF], g_w1l[DD*DFF];
__device__ unsigned short g_w2h[DFF*DD], g_w2l[DFF*DD];

// ---------------- PTX helpers (baseline sm_80+ features only) ----------------
__device__ __forceinline__ uint32_t smem_to_u32(const void* p) {
    uint32_t a;
    asm("{ .reg .u64 t; cvta.to.shared.u64 t, %1; cvt.u32.u64 %0, t; }" : "=r"(a) : "l"(p));
    return a;
}
__device__ __forceinline__ void cp_async16(uint32_t s, const void* g) {
    asm volatile("cp.async.cg.shared.global [%0], [%1], 16;" :: "r"(s), "l"(g) : "memory");
}
#define CP_COMMIT() asm volatile("cp.async.commit_group;" ::: "memory")
#define CP_WAIT_0() asm volatile("cp.async.wait_group 0;" ::: "memory")
#define CP_WAIT_1() asm volatile("cp.async.wait_group 1;" ::: "memory")

__device__ __forceinline__ void ldsm_x4(uint32_t addr, uint32_t r[4]) {
    asm volatile("ldmatrix.sync.aligned.m8n8.x4.shared.b16 {%0,%1,%2,%3}, [%4];"
                 : "=r"(r[0]), "=r"(r[1]), "=r"(r[2]), "=r"(r[3]) : "r"(addr));
}
__device__ __forceinline__ void mma_bf16(float d[4], const uint32_t a[4], const uint32_t b[2]) {
    asm volatile("mma.sync.aligned.m16n8k16.row.col.f32.bf16.bf16.f32 "
                 "{%0,%1,%2,%3}, {%4,%5,%6,%7}, {%8,%9}, {%0,%1,%2,%3};"
                 : "+f"(d[0]), "+f"(d[1]), "+f"(d[2]), "+f"(d[3])
                 : "r"(a[0]), "r"(a[1]), "r"(a[2]), "r"(a[3]), "r"(b[0]), "r"(b[1]));
}

__device__ __forceinline__ float gelu_exact(float v) {
    return 0.5f * v * (1.0f + erff(v * 0.70710678118654752f));
}
__device__ __forceinline__ void split_bf16(float v, __nv_bfloat16& h, __nv_bfloat16& l) {
    h = __float2bfloat16(v);
    l = __float2bfloat16(v - __bfloat162float(h));
}

// ---------------- LayerNorm -> bf16 hi/lo split ----------------
__global__ __launch_bounds__(256)
void ln_kernel(const float* __restrict__ x,
               const float* __restrict__ alpha,
               const float* __restrict__ beta,
               __nv_bfloat16* __restrict__ yh,
               __nv_bfloat16* __restrict__ yl)
{
    int row = blockIdx.x;
    int t = threadIdx.x;
    const float4* xr = (const float4*)(x + (size_t)row * DD);
    float4 v = xr[t];
    float s  = v.x + v.y + v.z + v.w;
    float sq = v.x*v.x + v.y*v.y + v.z*v.z + v.w*v.w;
    #pragma unroll
    for (int o = 16; o; o >>= 1) {
        s  += __shfl_xor_sync(0xffffffffu, s,  o);
        sq += __shfl_xor_sync(0xffffffffu, sq, o);
    }
    __shared__ float red[2][8];
    int w = t >> 5, lane = t & 31;
    if (lane == 0) { red[0][w] = s; red[1][w] = sq; }
    __syncthreads();
    if (t == 0) {
        float S = 0.f, Q = 0.f;
        #pragma unroll
        for (int i = 0; i < 8; i++) { S += red[0][i]; Q += red[1][i]; }
        float mean = S * (1.0f / DD);
        float var  = Q * (1.0f / DD) - mean * mean;
        red[0][0] = mean;
        red[1][0] = rsqrtf(var + 1e-5f);
    }
    __syncthreads();
    float mean = red[0][0], rstd = red[1][0];
    float4 a = ((const float4*)alpha)[t];
    float4 b = ((const float4*)beta)[t];
    float o0 = a.x * (v.x - mean) * rstd + b.x;
    float o1 = a.y * (v.y - mean) * rstd + b.y;
    float o2 = a.z * (v.z - mean) * rstd + b.z;
    float o3 = a.w * (v.w - mean) * rstd + b.w;
    __nv_bfloat16 h0,h1,h2,h3,l0,l1,l2,l3;
    split_bf16(o0,h0,l0); split_bf16(o1,h1,l1); split_bf16(o2,h2,l2); split_bf16(o3,h3,l3);
    size_t off = (size_t)row * DD + t * 4;
    ((__nv_bfloat162*)(yh + off))[0] = __halves2bfloat162(h0, h1);
    ((__nv_bfloat162*)(yh + off))[1] = __halves2bfloat162(h2, h3);
    ((__nv_bfloat162*)(yl + off))[0] = __halves2bfloat162(l0, l1);
    ((__nv_bfloat162*)(yl + off))[1] = __halves2bfloat162(l2, l3);
}

// ---------------- weight transpose + split: W[K,N] -> Wt_hi/lo[N,K] ----------------
__global__ __launch_bounds__(256)
void wsplit_kernel(const float* __restrict__ W,
                   __nv_bfloat16* __restrict__ Th,
                   __nv_bfloat16* __restrict__ Tl, int K, int N)
{
    __shared__ float t[32][33];
    int n0 = blockIdx.x * 32, k0 = blockIdx.y * 32;
    int tx = threadIdx.x & 31, ty = threadIdx.x >> 5;  // 32x8
    #pragma unroll
    for (int i = 0; i < 32; i += 8)
        t[ty + i][tx] = W[(size_t)(k0 + ty + i) * N + n0 + tx];
    __syncthreads();
    #pragma unroll
    for (int i = 0; i < 32; i += 8) {
        float v = t[tx][ty + i];
        __nv_bfloat16 h, l; split_bf16(v, h, l);
        size_t o = (size_t)(n0 + ty + i) * K + k0 + tx;
        Th[o] = h; Tl[o] = l;
    }
}

// ---------------- mma.sync split-bf16 GEMM ----------------
// C[M,N] = A[M,K] @ Bt[N,K]^T with A = Ah+Al, B = Bh+Bl (drop Al*Bl)
// CTA tile 128x128, BK=32, 8 warps (4 M x 2 N), warp tile 32x64.
// smem tiles: 128 rows x 32 bf16, row stride 40 halves (80 B) -> ldmatrix conflict-free.
#define BMT 128
#define BNT 128
#define BKT32 32
#define ROWB 80                       // padded row bytes (40 halves)
#define TILE_B (128 * ROWB)           // 10240 B
#define STAGE_B (4 * TILE_B)          // Ah, Al, Bh, Bl = 40960 B
#define GEMM_DSMEM (2 * STAGE_B + 128)

__device__ __forceinline__ void load_stage(
    uint32_t sbase, const __nv_bfloat16* Ah, const __nv_bfloat16* Al,
    const __nv_bfloat16* Bh, const __nv_bfloat16* Bl,
    int m0, int n0, int k0, int K, int tid)
{
    #pragma unroll
    for (int u = 0; u < 8; u++) {
        int cid = tid + u * 256;          // 0..2047
        int tile = cid >> 9;              // 0..3
        int rem = cid & 511;
        int r = rem >> 2, c = rem & 3;    // row 0..127, 16B-chunk 0..3
        const __nv_bfloat16* src = (tile == 0) ? Ah : (tile == 1) ? Al : (tile == 2) ? Bh : Bl;
        int row = ((tile < 2) ? m0 : n0) + r;
        const __nv_bfloat16* g = src + (size_t)row * K + k0 + c * 8;
        uint32_t s = sbase + tile * TILE_B + r * ROWB + c * 16;
        cp_async16(s, g);
    }
}

template<int EPI>
__global__ __launch_bounds__(256)
void tc_gemm(const __nv_bfloat16* __restrict__ Ah, const __nv_bfloat16* __restrict__ Al,
             const __nv_bfloat16* __restrict__ Bh, const __nv_bfloat16* __restrict__ Bl,
             const float* __restrict__ bias, const float* __restrict__ res,
             float* __restrict__ C,
             __nv_bfloat16* __restrict__ Ch, __nv_bfloat16* __restrict__ Cl,
             int M, int N, int K)
{
    extern __shared__ __align__(128) char dsm[];
    uint32_t sb = smem_to_u32(dsm);

    int tid = threadIdx.x, wid = tid >> 5, lid = tid & 31;
    int n0 = blockIdx.x * BNT, m0 = blockIdx.y * BMT;
    int wm = (wid >> 1) * 32;     // warp M offset inside CTA tile
    int wn = (wid & 1) * 64;      // warp N offset

    float acc[2][8][4];
    #pragma unroll
    for (int mt = 0; mt < 2; mt++)
        #pragma unroll
        for (int nt = 0; nt < 8; nt++)
            #pragma unroll
            for (int j = 0; j < 4; j++) acc[mt][nt][j] = 0.0f;

    // ldmatrix per-lane source rows/cols
    int a_row = ((lid >> 3) & 1) * 8 + (lid & 7);      // + mt*16 + wm
    int a_colh = (lid >> 4) * 8;                       // + ks*16 (halves)
    int b_row = (lid >> 4) * 8 + (lid & 7);            // + ng*16 + wn
    int b_colh = ((lid >> 3) & 1) * 8;                 // + ks*16

    int nch = K / BKT32;

    load_stage(sb, Ah, Al, Bh, Bl, m0, n0, 0, K, tid);
    CP_COMMIT();

    for (int i = 0; i < nch; i++) {
        uint32_t st = sb + (uint32_t)(i & 1) * STAGE_B;
        if (i + 1 < nch) {
            load_stage(sb + (uint32_t)((i + 1) & 1) * STAGE_B,
                       Ah, Al, Bh, Bl, m0, n0, (i + 1) * BKT32, K, tid);
            CP_COMMIT();
            CP_WAIT_1();
        } else {
            CP_WAIT_0();
        }
        __syncthreads();

        uint32_t tAh = st;
        uint32_t tAl = st + TILE_B;
        uint32_t tBh = st + 2 * TILE_B;
        uint32_t tBl = st + 3 * TILE_B;

        #pragma unroll
        for (int ks = 0; ks < 2; ks++) {
            uint32_t ah[2][4], al[2][4], bh[8][2], bl[8][2];
            #pragma unroll
            for (int mt = 0; mt < 2; mt++) {
                uint32_t ra = (uint32_t)((wm + mt * 16 + a_row) * ROWB + (ks * 16 + a_colh) * 2);
                ldsm_x4(tAh + ra, ah[mt]);
                ldsm_x4(tAl + ra, al[mt]);
            }
            #pragma unroll
            for (int ng = 0; ng < 4; ng++) {
                uint32_t rb = (uint32_t)((wn + ng * 16 + b_row) * ROWB + (ks * 16 + b_colh) * 2);
                uint32_t t4[4];
                ldsm_x4(tBh + rb, t4);
                bh[2*ng][0] = t4[0]; bh[2*ng][1] = t4[1];
                bh[2*ng+1][0] = t4[2]; bh[2*ng+1][1] = t4[3];
                ldsm_x4(tBl + rb, t4);
                bl[2*ng][0] = t4[0]; bl[2*ng][1] = t4[1];
                bl[2*ng+1][0] = t4[2]; bl[2*ng+1][1] = t4[3];
            }
            #pragma unroll
            for (int mt = 0; mt < 2; mt++)
                #pragma unroll
                for (int nt = 0; nt < 8; nt++) {
                    mma_bf16(acc[mt][nt], ah[mt], bh[nt]);
                    mma_bf16(acc[mt][nt], ah[mt], bl[nt]);
                    mma_bf16(acc[mt][nt], al[mt], bh[nt]);
                }
        }
        __syncthreads();
    }

    // ---------------- epilogue ----------------
    int g = lid >> 2, t4i = lid & 3;
    #pragma unroll
    for (int mt = 0; mt < 2; mt++) {
        #pragma unroll
        for (int nt = 0; nt < 8; nt++) {
            int row0 = m0 + wm + mt * 16 + g;
            int row1 = row0 + 8;
            int col  = n0 + wn + nt * 8 + 2 * t4i;
            float d0 = acc[mt][nt][0], d1 = acc[mt][nt][1];
            float d2 = acc[mt][nt][2], d3 = acc[mt][nt][3];
            if (EPI == 2 || EPI == 3) {
                float2 bv = *(const float2*)(bias + col);
                d0 += bv.x; d1 += bv.y; d2 += bv.x; d3 += bv.y;
            }
            if (EPI == 2) {
                d0 = gelu_exact(d0); d1 = gelu_exact(d1);
                d2 = gelu_exact(d2); d3 = gelu_exact(d3);
            }
            if (EPI == 1 || EPI == 3) {
                float2 r0 = *(const float2*)(res + (size_t)row0 * N + col);
                float2 r1 = *(const float2*)(res + (size_t)row1 * N + col);
                d0 += r0.x; d1 += r0.y; d2 += r1.x; d3 += r1.y;
            }
            if (EPI == 2) {
                __nv_bfloat16 h0,h1,h2,h3,l0,l1,l2,l3;
                split_bf16(d0,h0,l0); split_bf16(d1,h1,l1);
                split_bf16(d2,h2,l2); split_bf16(d3,h3,l3);
                *(__nv_bfloat162*)(Ch + (size_t)row0 * N + col) = __halves2bfloat162(h0, h1);
                *(__nv_bfloat162*)(Cl + (size_t)row0 * N + col) = __halves2bfloat162(l0, l1);
                *(__nv_bfloat162*)(Ch + (size_t)row1 * N + col) = __halves2bfloat162(h2, h3);
                *(__nv_bfloat162*)(Cl + (size_t)row1 * N + col) = __halves2bfloat162(l2, l3);
            } else {
                *(float2*)(C + (size_t)row0 * N + col) = make_float2(d0, d1);
                *(float2*)(C + (size_t)row1 * N + col) = make_float2(d2, d3);
            }
        }
    }
}

// ---------------- Flash attention, fp32, BQ=BK=64, dh=64 ----------------
#define BQ  64
#define BKT 64
#define ATTN_SMEM (4 * BQ * DH * (int)sizeof(float) + BKT * (int)sizeof(int))

__global__ __launch_bounds__(256)
void attn_kernel(const float* __restrict__ Qg, const float* __restrict__ Kg,
                 const float* __restrict__ Vg, const int* __restrict__ amask,
                 __nv_bfloat16* __restrict__ ch, __nv_bfloat16* __restrict__ cl)
{
    extern __shared__ __align__(16) float sh[];
    float* Qs  = sh;
    float* KsT = Qs  + BQ * DH;
    float* Vs  = KsT + DH * BKT;
    float* Ps  = Vs  + BKT * DH;
    int*   mks = (int*)(Ps + BQ * BKT);

    int tid = threadIdx.x;
    int qt = blockIdx.x, h = blockIdx.y, b = blockIdx.z;
    int q0 = qt * BQ;
    int ty = tid >> 4, tx = tid & 15;

    {
        int r = tid >> 2; int c0 = (tid & 3) * 16;
        const float4* src = (const float4*)(Qg + ((size_t)(b * SS + q0 + r)) * DD + h * DH + c0);
        float4* dst = (float4*)(Qs + r * DH + c0);
        dst[0] = src[0]; dst[1] = src[1]; dst[2] = src[2]; dst[3] = src[3];
    }

    int mq[4];
    #pragma unroll
    for (int i = 0; i < 4; i++) mq[i] = amask[b * SS + q0 + ty * 4 + i];

    float m[4], l[4], o[4][4];
    #pragma unroll
    for (int i = 0; i < 4; i++) {
        m[i] = -1e30f; l[i] = 0.0f;
        #pragma unroll
        for (int j = 0; j < 4; j++) o[i][j] = 0.0f;
    }

    int ntiles = qt + 1;
    for (int t = 0; t < ntiles; t++) {
        int k0 = t * BKT;
        __syncthreads();
        {
            int r = tid >> 2; int c0 = (tid & 3) * 16;
            const float* ksrc = Kg + ((size_t)(b * SS + k0 + r)) * DD + h * DH;
            #pragma unroll
            for (int c = 0; c < 16; c += 4) {
                float4 kv = *(const float4*)(ksrc + c0 + c);
                KsT[(c0 + c + 0) * BKT + r] = kv.x;
                KsT[(c0 + c + 1) * BKT + r] = kv.y;
                KsT[(c0 + c + 2) * BKT + r] = kv.z;
                KsT[(c0 + c + 3) * BKT + r] = kv.w;
            }
            const float4* vsrc = (const float4*)(Vg + ((size_t)(b * SS + k0 + r)) * DD + h * DH + c0);
            float4* vdst = (float4*)(Vs + r * DH + c0);
            vdst[0] = vsrc[0]; vdst[1] = vsrc[1]; vdst[2] = vsrc[2]; vdst[3] = vsrc[3];
            if (tid < BKT) mks[tid] = amask[b * SS + k0 + tid];
        }
        __syncthreads();

        float s[4][4];
        #pragma unroll
        for (int i = 0; i < 4; i++)
            #pragma unroll
            for (int j = 0; j < 4; j++) s[i][j] = 0.0f;

        #pragma unroll 4
        for (int d = 0; d < DH; d += 4) {
            float4 q4[4], k4[4];
            #pragma unroll
            for (int i = 0; i < 4; i++)  q4[i]  = *(const float4*)&Qs[(ty * 4 + i) * DH + d];
            #pragma unroll
            for (int dd = 0; dd < 4; dd++) k4[dd] = *(const float4*)&KsT[(d + dd) * BKT + tx * 4];
            #pragma unroll
            for (int i = 0; i < 4; i++) {
                s[i][0] += q4[i].x * k4[0].x + q4[i].y * k4[1].x + q4[i].z * k4[2].x + q4[i].w * k4[3].x;
                s[i][1] += q4[i].x * k4[0].y + q4[i].y * k4[1].y + q4[i].z * k4[2].y + q4[i].w * k4[3].y;
                s[i][2] += q4[i].x * k4[0].z + q4[i].y * k4[1].z + q4[i].z * k4[2].z + q4[i].w * k4[3].z;
                s[i][3] += q4[i].x * k4[0].w + q4[i].y * k4[1].w + q4[i].z * k4[2].w + q4[i].w * k4[3].w;
            }
        }

        const float scale = 0.125f;
        #pragma unroll
        for (int i = 0; i < 4; i++) {
            int qg = q0 + ty * 4 + i;
            #pragma unroll
            for (int j = 0; j < 4; j++) {
                int kloc = tx * 4 + j;
                int kg = k0 + kloc;
                float v = s[i][j] * scale;
                if (kg > qg || mks[kloc] == 0 || mq[i] == 0) v = -1e30f;
                s[i][j] = v;
            }
            float mt = fmaxf(fmaxf(s[i][0], s[i][1]), fmaxf(s[i][2], s[i][3]));
            #pragma unroll
            for (int off = 8; off; off >>= 1)
                mt = fmaxf(mt, __shfl_xor_sync(0xffffffffu, mt, off));
            float mn = fmaxf(m[i], mt);
            float corr = __expf(m[i] - mn);
            m[i] = mn;
            float rs = 0.0f;
            #pragma unroll
            for (int j = 0; j < 4; j++) {
                float p = __expf(s[i][j] - mn);
                s[i][j] = p; rs += p;
            }
            #pragma unroll
            for (int off = 8; off; off >>= 1)
                rs += __shfl_xor_sync(0xffffffffu, rs, off);
            l[i] = l[i] * corr + rs;
            #pragma unroll
            for (int j = 0; j < 4; j++) o[i][j] *= corr;
            *(float4*)&Ps[(ty * 4 + i) * BKT + tx * 4] =
                make_float4(s[i][0], s[i][1], s[i][2], s[i][3]);
        }
        __syncthreads();

        #pragma unroll 4
        for (int k = 0; k < BKT; k += 4) {
            float4 p4[4], v4[4];
            #pragma unroll
            for (int i = 0; i < 4; i++)  p4[i]  = *(const float4*)&Ps[(ty * 4 + i) * BKT + k];
            #pragma unroll
            for (int kk = 0; kk < 4; kk++) v4[kk] = *(const float4*)&Vs[(k + kk) * DH + tx * 4];
            #pragma unroll
            for (int i = 0; i < 4; i++) {
                o[i][0] += p4[i].x * v4[0].x + p4[i].y * v4[1].x + p4[i].z * v4[2].x + p4[i].w * v4[3].x;
                o[i][1] += p4[i].x * v4[0].y + p4[i].y * v4[1].y + p4[i].z * v4[2].y + p4[i].w * v4[3].y;
                o[i][2] += p4[i].x * v4[0].z + p4[i].y * v4[1].z + p4[i].z * v4[2].z + p4[i].w * v4[3].z;
                o[i][3] += p4[i].x * v4[0].w + p4[i].y * v4[1].w + p4[i].z * v4[2].w + p4[i].w * v4[3].w;
            }
        }
    }

    #pragma unroll
    for (int i = 0; i < 4; i++) {
        float inv = 1.0f / l[i];
        size_t off = ((size_t)(b * SS + q0 + ty * 4 + i)) * DD + h * DH + tx * 4;
        float v0 = o[i][0] * inv, v1 = o[i][1] * inv, v2 = o[i][2] * inv, v3 = o[i][3] * inv;
        __nv_bfloat16 h0,h1,h2,h3,l0,l1,l2,l3;
        split_bf16(v0,h0,l0); split_bf16(v1,h1,l1); split_bf16(v2,h2,l2); split_bf16(v3,h3,l3);
        ((__nv_bfloat162*)(ch + off))[0] = __halves2bfloat162(h0, h1);
        ((__nv_bfloat162*)(ch + off))[1] = __halves2bfloat162(h2, h3);
        ((__nv_bfloat162*)(cl + off))[0] = __halves2bfloat162(l0, l1);
        ((__nv_bfloat162*)(cl + off))[1] = __halves2bfloat162(l2, l3);
    }
}

// ---------------- orchestration ----------------
extern "C" void kernel_launch(void* const* d_in, const int* in_sizes, int n_in,
                              void* d_out, int out_size)
{
    const float* x    = (const float*)d_in[0];
    const int*   am   = (const int*)  d_in[1];
    const float* ln1a = (const float*)d_in[2];
    const float* ln1b = (const float*)d_in[3];
    const float* ln2a = (const float*)d_in[4];
    const float* ln2b = (const float*)d_in[5];
    const float* Wq   = (const float*)d_in[6];
    const float* Wk   = (const float*)d_in[7];
    const float* Wv   = (const float*)d_in[8];
    const float* Wo   = (const float*)d_in[9];
    const float* W1   = (const float*)d_in[10];
    const float* b1   = (const float*)d_in[11];
    const float* W2   = (const float*)d_in[12];
    const float* b2   = (const float*)d_in[13];
    float* out = (float*)d_out;

    float *q, *k, *v, *x1;
    cudaGetSymbolAddress((void**)&q,  g_q);
    cudaGetSymbolAddress((void**)&k,  g_k);
    cudaGetSymbolAddress((void**)&v,  g_v);
    cudaGetSymbolAddress((void**)&x1, g_x1);

    __nv_bfloat16 *yh,*yl,*ch,*cl,*y2h,*y2l,*hh,*hl;
    __nv_bfloat16 *wqh,*wql,*wkh,*wkl,*wvh,*wvl,*woh,*wol,*w1h,*w1l,*w2h,*w2l;
    cudaGetSymbolAddress((void**)&yh,  g_yh);  cudaGetSymbolAddress((void**)&yl,  g_yl);
    cudaGetSymbolAddress((void**)&ch,  g_ch);  cudaGetSymbolAddress((void**)&cl,  g_cl);
    cudaGetSymbolAddress((void**)&y2h, g_y2h); cudaGetSymbolAddress((void**)&y2l, g_y2l);
    cudaGetSymbolAddress((void**)&hh,  g_hh);  cudaGetSymbolAddress((void**)&hl,  g_hl);
    cudaGetSymbolAddress((void**)&wqh, g_wqh); cudaGetSymbolAddress((void**)&wql, g_wql);
    cudaGetSymbolAddress((void**)&wkh, g_wkh); cudaGetSymbolAddress((void**)&wkl, g_wkl);
    cudaGetSymbolAddress((void**)&wvh, g_wvh); cudaGetSymbolAddress((void**)&wvl, g_wvl);
    cudaGetSymbolAddress((void**)&woh, g_woh); cudaGetSymbolAddress((void**)&wol, g_wol);
    cudaGetSymbolAddress((void**)&w1h, g_w1h); cudaGetSymbolAddress((void**)&w1l, g_w1l);
    cudaGetSymbolAddress((void**)&w2h, g_w2h); cudaGetSymbolAddress((void**)&w2l, g_w2l);

    cudaFuncSetAttribute(attn_kernel, cudaFuncAttributeMaxDynamicSharedMemorySize, ATTN_SMEM);
    cudaFuncSetAttribute(tc_gemm<0>, cudaFuncAttributeMaxDynamicSharedMemorySize, GEMM_DSMEM);
    cudaFuncSetAttribute(tc_gemm<1>, cudaFuncAttributeMaxDynamicSharedMemorySize, GEMM_DSMEM);
    cudaFuncSetAttribute(tc_gemm<2>, cudaFuncAttributeMaxDynamicSharedMemorySize, GEMM_DSMEM);
    cudaFuncSetAttribute(tc_gemm<3>, cudaFuncAttributeMaxDynamicSharedMemorySize, GEMM_DSMEM);

    // weight transpose + split
    wsplit_kernel<<<dim3(DD/32,  DD/32),  256>>>(Wq, wqh, wql, DD,  DD);
    wsplit_kernel<<<dim3(DD/32,  DD/32),  256>>>(Wk, wkh, wkl, DD,  DD);
    wsplit_kernel<<<dim3(DD/32,  DD/32),  256>>>(Wv, wvh, wvl, DD,  DD);
    wsplit_kernel<<<dim3(DD/32,  DD/32),  256>>>(Wo, woh, wol, DD,  DD);
    wsplit_kernel<<<dim3(DFF/32, DD/32),  256>>>(W1, w1h, w1l, DD,  DFF);
    wsplit_kernel<<<dim3(DD/32,  DFF/32), 256>>>(W2, w2h, w2l, DFF, DD);

    dim3 gD(DD / BNT,  MTOT / BMT);   // (8, 64)
    dim3 gF(DFF / BNT, MTOT / BMT);   // (32, 64)

    // LN1 -> split
    ln_kernel<<<MTOT, 256>>>(x, ln1a, ln1b, yh, yl);
    // QKV projections (fp32 out for attention)
    tc_gemm<0><<<gD, 256, GEMM_DSMEM>>>(yh, yl, wqh, wql, nullptr, nullptr, q, nullptr, nullptr, MTOT, DD, DD);
    tc_gemm<0><<<gD, 256, GEMM_DSMEM>>>(yh, yl, wkh, wkl, nullptr, nullptr, k, nullptr, nullptr, MTOT, DD, DD);
    tc_gemm<0><<<gD, 256, GEMM_DSMEM>>>(yh, yl, wvh, wvl, nullptr, nullptr, v, nullptr, nullptr, MTOT, DD, DD);
    // attention -> ctx split
    attn_kernel<<<dim3(SS / BQ, HH, BB), 256, ATTN_SMEM>>>(q, k, v, am, ch, cl);
    // output projection + residual
    tc_gemm<1><<<gD, 256, GEMM_DSMEM>>>(ch, cl, woh, wol, nullptr, x, x1, nullptr, nullptr, MTOT, DD, DD);
    // LN2 -> split
    ln_kernel<<<MTOT, 256>>>(x1, ln2a, ln2b, y2h, y2l);
    // FFN up + bias + GELU -> split
    tc_gemm<2><<<gF, 256, GEMM_DSMEM>>>(y2h, y2l, w1h, w1l, b1, nullptr, nullptr, hh, hl, MTOT, DFF, DD);
    // FFN down + bias + residual -> output
    tc_gemm<3><<<gD, 256, GEMM_DSMEM>>>(hh, hl, w2h, w2l, b2, x1, out, nullptr, nullptr, MTOT, DD, DFF);
}

// round 9
// speedup vs baseline: 2.9808x; 1.5471x over previous
#include <cuda_runtime.h>
#include <cuda_bf16.h>
#include <cuda_fp16.h>
#include <cstdint>
#include <math.h>

// ---------------- problem constants ----------------
#define BB   4
#define SS   2048
#define DD   1024
#define HH   16
#define DH   64
#define DFF  4096
#define MTOT (BB*SS)   // 8192 rows

// ---------------- scratch (device globals; no allocations allowed) ----------
// g_q/g_k/g_v reused as fp16 (half of the fp32 footprint)
__device__ float g_q [MTOT*DD];
__device__ float g_k [MTOT*DD];
__device__ float g_v [MTOT*DD];
__device__ float g_x1[MTOT*DD];

__device__ unsigned short g_yh [MTOT*DD],  g_yl [MTOT*DD];
__device__ unsigned short g_ch [MTOT*DD],  g_cl [MTOT*DD];
__device__ unsigned short g_y2h[MTOT*DD],  g_y2l[MTOT*DD];
__device__ unsigned short g_hh [MTOT*DFF], g_hl [MTOT*DFF];

__device__ unsigned short g_wqh[DD*DD],  g_wql[DD*DD];
__device__ unsigned short g_wkh[DD*DD],  g_wkl[DD*DD];
__device__ unsigned short g_wvh[DD*DD],  g_wvl[DD*DD];
__device__ unsigned short g_woh[DD*DD],  g_wol[DD*DD];
__device__ unsigned short g_w1h[DD*DFF], g_w1l[DD*DFF];
__device__ unsigned short g_w2h[DFF*DD], g_w2l[DFF*DD];

// ---------------- PTX helpers (baseline sm_80+ features only) ----------------
__device__ __forceinline__ uint32_t smem_to_u32(const void* p) {
    uint32_t a;
    asm("{ .reg .u64 t; cvta.to.shared.u64 t, %1; cvt.u32.u64 %0, t; }" : "=r"(a) : "l"(p));
    return a;
}
__device__ __forceinline__ void cp_async16(uint32_t s, const void* g) {
    asm volatile("cp.async.cg.shared.global [%0], [%1], 16;" :: "r"(s), "l"(g) : "memory");
}
#define CP_COMMIT() asm volatile("cp.async.commit_group;" ::: "memory")
#define CP_WAIT_0() asm volatile("cp.async.wait_group 0;" ::: "memory")
#define CP_WAIT_1() asm volatile("cp.async.wait_group 1;" ::: "memory")

__device__ __forceinline__ void ldsm_x4(uint32_t addr, uint32_t r[4]) {
    asm volatile("ldmatrix.sync.aligned.m8n8.x4.shared.b16 {%0,%1,%2,%3}, [%4];"
                 : "=r"(r[0]), "=r"(r[1]), "=r"(r[2]), "=r"(r[3]) : "r"(addr));
}
__device__ __forceinline__ void ldsm_x4_t(uint32_t addr, uint32_t r[4]) {
    asm volatile("ldmatrix.sync.aligned.m8n8.x4.trans.shared.b16 {%0,%1,%2,%3}, [%4];"
                 : "=r"(r[0]), "=r"(r[1]), "=r"(r[2]), "=r"(r[3]) : "r"(addr));
}
__device__ __forceinline__ void mma_bf16(float d[4], const uint32_t a[4], const uint32_t b[2]) {
    asm volatile("mma.sync.aligned.m16n8k16.row.col.f32.bf16.bf16.f32 "
                 "{%0,%1,%2,%3}, {%4,%5,%6,%7}, {%8,%9}, {%0,%1,%2,%3};"
                 : "+f"(d[0]), "+f"(d[1]), "+f"(d[2]), "+f"(d[3])
                 : "r"(a[0]), "r"(a[1]), "r"(a[2]), "r"(a[3]), "r"(b[0]), "r"(b[1]));
}
__device__ __forceinline__ void mma_fp16(float d[4], const uint32_t a[4], const uint32_t b[2]) {
    asm volatile("mma.sync.aligned.m16n8k16.row.col.f32.f16.f16.f32 "
                 "{%0,%1,%2,%3}, {%4,%5,%6,%7}, {%8,%9}, {%0,%1,%2,%3};"
                 : "+f"(d[0]), "+f"(d[1]), "+f"(d[2]), "+f"(d[3])
                 : "r"(a[0]), "r"(a[1]), "r"(a[2]), "r"(a[3]), "r"(b[0]), "r"(b[1]));
}

__device__ __forceinline__ float gelu_exact(float v) {
    return 0.5f * v * (1.0f + erff(v * 0.70710678118654752f));
}
__device__ __forceinline__ void split_bf16(float v, __nv_bfloat16& h, __nv_bfloat16& l) {
    h = __float2bfloat16(v);
    l = __float2bfloat16(v - __bfloat162float(h));
}
__device__ __forceinline__ uint32_t pack_h2(float a, float b) {
    __half2 h = __floats2half2_rn(a, b);
    return *reinterpret_cast<uint32_t*>(&h);
}

// ---------------- LayerNorm -> bf16 hi/lo split ----------------
__global__ __launch_bounds__(256)
void ln_kernel(const float* __restrict__ x,
               const float* __restrict__ alpha,
               const float* __restrict__ beta,
               __nv_bfloat16* __restrict__ yh,
               __nv_bfloat16* __restrict__ yl)
{
    int row = blockIdx.x;
    int t = threadIdx.x;
    const float4* xr = (const float4*)(x + (size_t)row * DD);
    float4 v = xr[t];
    float s  = v.x + v.y + v.z + v.w;
    float sq = v.x*v.x + v.y*v.y + v.z*v.z + v.w*v.w;
    #pragma unroll
    for (int o = 16; o; o >>= 1) {
        s  += __shfl_xor_sync(0xffffffffu, s,  o);
        sq += __shfl_xor_sync(0xffffffffu, sq, o);
    }
    __shared__ float red[2][8];
    int w = t >> 5, lane = t & 31;
    if (lane == 0) { red[0][w] = s; red[1][w] = sq; }
    __syncthreads();
    if (t == 0) {
        float S = 0.f, Q = 0.f;
        #pragma unroll
        for (int i = 0; i < 8; i++) { S += red[0][i]; Q += red[1][i]; }
        float mean = S * (1.0f / DD);
        float var  = Q * (1.0f / DD) - mean * mean;
        red[0][0] = mean;
        red[1][0] = rsqrtf(var + 1e-5f);
    }
    __syncthreads();
    float mean = red[0][0], rstd = red[1][0];
    float4 a = ((const float4*)alpha)[t];
    float4 b = ((const float4*)beta)[t];
    float o0 = a.x * (v.x - mean) * rstd + b.x;
    float o1 = a.y * (v.y - mean) * rstd + b.y;
    float o2 = a.z * (v.z - mean) * rstd + b.z;
    float o3 = a.w * (v.w - mean) * rstd + b.w;
    __nv_bfloat16 h0,h1,h2,h3,l0,l1,l2,l3;
    split_bf16(o0,h0,l0); split_bf16(o1,h1,l1); split_bf16(o2,h2,l2); split_bf16(o3,h3,l3);
    size_t off = (size_t)row * DD + t * 4;
    ((__nv_bfloat162*)(yh + off))[0] = __halves2bfloat162(h0, h1);
    ((__nv_bfloat162*)(yh + off))[1] = __halves2bfloat162(h2, h3);
    ((__nv_bfloat162*)(yl + off))[0] = __halves2bfloat162(l0, l1);
    ((__nv_bfloat162*)(yl + off))[1] = __halves2bfloat162(l2, l3);
}

// ---------------- weight transpose + split: W[K,N] -> Wt_hi/lo[N,K] ----------------
__global__ __launch_bounds__(256)
void wsplit_kernel(const float* __restrict__ W,
                   __nv_bfloat16* __restrict__ Th,
                   __nv_bfloat16* __restrict__ Tl, int K, int N)
{
    __shared__ float t[32][33];
    int n0 = blockIdx.x * 32, k0 = blockIdx.y * 32;
    int tx = threadIdx.x & 31, ty = threadIdx.x >> 5;  // 32x8
    #pragma unroll
    for (int i = 0; i < 32; i += 8)
        t[ty + i][tx] = W[(size_t)(k0 + ty + i) * N + n0 + tx];
    __syncthreads();
    #pragma unroll
    for (int i = 0; i < 32; i += 8) {
        float v = t[tx][ty + i];
        __nv_bfloat16 h, l; split_bf16(v, h, l);
        size_t o = (size_t)(n0 + ty + i) * K + k0 + tx;
        Th[o] = h; Tl[o] = l;
    }
}

// ---------------- mma.sync split-bf16 GEMM (unchanged core) ----------------
// EPI 0: C fp32 = acc
// EPI 1: C fp32 = res + acc
// EPI 2: Ch/Cl bf16 split of gelu(acc + bias)
// EPI 3: C fp32 = res + acc + bias
// EPI 4: (half*)Ch = fp16(acc)
#define BMT 128
#define BNT 128
#define BKT32 32
#define ROWB 80
#define TILE_B (128 * ROWB)
#define STAGE_B (4 * TILE_B)
#define GEMM_DSMEM (2 * STAGE_B + 128)

__device__ __forceinline__ void load_stage(
    uint32_t sbase, const __nv_bfloat16* Ah, const __nv_bfloat16* Al,
    const __nv_bfloat16* Bh, const __nv_bfloat16* Bl,
    int m0, int n0, int k0, int K, int tid)
{
    #pragma unroll
    for (int u = 0; u < 8; u++) {
        int cid = tid + u * 256;
        int tile = cid >> 9;
        int rem = cid & 511;
        int r = rem >> 2, c = rem & 3;
        const __nv_bfloat16* src = (tile == 0) ? Ah : (tile == 1) ? Al : (tile == 2) ? Bh : Bl;
        int row = ((tile < 2) ? m0 : n0) + r;
        const __nv_bfloat16* g = src + (size_t)row * K + k0 + c * 8;
        uint32_t s = sbase + tile * TILE_B + r * ROWB + c * 16;
        cp_async16(s, g);
    }
}

template<int EPI>
__global__ __launch_bounds__(256)
void tc_gemm(const __nv_bfloat16* __restrict__ Ah, const __nv_bfloat16* __restrict__ Al,
             const __nv_bfloat16* __restrict__ Bh, const __nv_bfloat16* __restrict__ Bl,
             const float* __restrict__ bias, const float* __restrict__ res,
             float* __restrict__ C,
             __nv_bfloat16* __restrict__ Ch, __nv_bfloat16* __restrict__ Cl,
             int M, int N, int K)
{
    extern __shared__ __align__(128) char dsm[];
    uint32_t sb = smem_to_u32(dsm);

    int tid = threadIdx.x, wid = tid >> 5, lid = tid & 31;
    int n0 = blockIdx.x * BNT, m0 = blockIdx.y * BMT;
    int wm = (wid >> 1) * 32;
    int wn = (wid & 1) * 64;

    float acc[2][8][4];
    #pragma unroll
    for (int mt = 0; mt < 2; mt++)
        #pragma unroll
        for (int nt = 0; nt < 8; nt++)
            #pragma unroll
            for (int j = 0; j < 4; j++) acc[mt][nt][j] = 0.0f;

    int a_row = ((lid >> 3) & 1) * 8 + (lid & 7);
    int a_colh = (lid >> 4) * 8;
    int b_row = (lid >> 4) * 8 + (lid & 7);
    int b_colh = ((lid >> 3) & 1) * 8;

    int nch = K / BKT32;

    load_stage(sb, Ah, Al, Bh, Bl, m0, n0, 0, K, tid);
    CP_COMMIT();

    for (int i = 0; i < nch; i++) {
        uint32_t st = sb + (uint32_t)(i & 1) * STAGE_B;
        if (i + 1 < nch) {
            load_stage(sb + (uint32_t)((i + 1) & 1) * STAGE_B,
                       Ah, Al, Bh, Bl, m0, n0, (i + 1) * BKT32, K, tid);
            CP_COMMIT();
            CP_WAIT_1();
        } else {
            CP_WAIT_0();
        }
        __syncthreads();

        uint32_t tAh = st;
        uint32_t tAl = st + TILE_B;
        uint32_t tBh = st + 2 * TILE_B;
        uint32_t tBl = st + 3 * TILE_B;

        #pragma unroll
        for (int ks = 0; ks < 2; ks++) {
            uint32_t ah[2][4], al[2][4], bh[8][2], bl[8][2];
            #pragma unroll
            for (int mt = 0; mt < 2; mt++) {
                uint32_t ra = (uint32_t)((wm + mt * 16 + a_row) * ROWB + (ks * 16 + a_colh) * 2);
                ldsm_x4(tAh + ra, ah[mt]);
                ldsm_x4(tAl + ra, al[mt]);
            }
            #pragma unroll
            for (int ng = 0; ng < 4; ng++) {
                uint32_t rb = (uint32_t)((wn + ng * 16 + b_row) * ROWB + (ks * 16 + b_colh) * 2);
                uint32_t t4[4];
                ldsm_x4(tBh + rb, t4);
                bh[2*ng][0] = t4[0]; bh[2*ng][1] = t4[1];
                bh[2*ng+1][0] = t4[2]; bh[2*ng+1][1] = t4[3];
                ldsm_x4(tBl + rb, t4);
                bl[2*ng][0] = t4[0]; bl[2*ng][1] = t4[1];
                bl[2*ng+1][0] = t4[2]; bl[2*ng+1][1] = t4[3];
            }
            #pragma unroll
            for (int mt = 0; mt < 2; mt++)
                #pragma unroll
                for (int nt = 0; nt < 8; nt++) {
                    mma_bf16(acc[mt][nt], ah[mt], bh[nt]);
                    mma_bf16(acc[mt][nt], ah[mt], bl[nt]);
                    mma_bf16(acc[mt][nt], al[mt], bh[nt]);
                }
        }
        __syncthreads();
    }

    int g = lid >> 2, t4i = lid & 3;
    #pragma unroll
    for (int mt = 0; mt < 2; mt++) {
        #pragma unroll
        for (int nt = 0; nt < 8; nt++) {
            int row0 = m0 + wm + mt * 16 + g;
            int row1 = row0 + 8;
            int col  = n0 + wn + nt * 8 + 2 * t4i;
            float d0 = acc[mt][nt][0], d1 = acc[mt][nt][1];
            float d2 = acc[mt][nt][2], d3 = acc[mt][nt][3];
            if (EPI == 2 || EPI == 3) {
                float2 bv = *(const float2*)(bias + col);
                d0 += bv.x; d1 += bv.y; d2 += bv.x; d3 += bv.y;
            }
            if (EPI == 2) {
                d0 = gelu_exact(d0); d1 = gelu_exact(d1);
                d2 = gelu_exact(d2); d3 = gelu_exact(d3);
            }
            if (EPI == 1 || EPI == 3) {
                float2 r0 = *(const float2*)(res + (size_t)row0 * N + col);
                float2 r1 = *(const float2*)(res + (size_t)row1 * N + col);
                d0 += r0.x; d1 += r0.y; d2 += r1.x; d3 += r1.y;
            }
            if (EPI == 2) {
                __nv_bfloat16 h0,h1,h2,h3,l0,l1,l2,l3;
                split_bf16(d0,h0,l0); split_bf16(d1,h1,l1);
                split_bf16(d2,h2,l2); split_bf16(d3,h3,l3);
                *(__nv_bfloat162*)(Ch + (size_t)row0 * N + col) = __halves2bfloat162(h0, h1);
                *(__nv_bfloat162*)(Cl + (size_t)row0 * N + col) = __halves2bfloat162(l0, l1);
                *(__nv_bfloat162*)(Ch + (size_t)row1 * N + col) = __halves2bfloat162(h2, h3);
                *(__nv_bfloat162*)(Cl + (size_t)row1 * N + col) = __halves2bfloat162(l2, l3);
            } else if (EPI == 4) {
                __half* Hf = (__half*)Ch;
                *(__half2*)(Hf + (size_t)row0 * N + col) = __floats2half2_rn(d0, d1);
                *(__half2*)(Hf + (size_t)row1 * N + col) = __floats2half2_rn(d2, d3);
            } else {
                *(float2*)(C + (size_t)row0 * N + col) = make_float2(d0, d1);
                *(float2*)(C + (size_t)row1 * N + col) = make_float2(d2, d3);
            }
        }
    }
}

// ---------------- fp16 mma.sync flash attention ----------------
// Grid (SS/64, HH, BB), 128 threads = 4 warps, each warp owns 16 q-rows.
// smem rows padded to 72 halves (144 B) -> conflict-free ldmatrix.
#define AQ   64
#define AKV  64
#define AROW 72   // halves per smem row

__global__ __launch_bounds__(128)
void attn_mma_kernel(const __half* __restrict__ Qg, const __half* __restrict__ Kg,
                     const __half* __restrict__ Vg, const int* __restrict__ amask,
                     __nv_bfloat16* __restrict__ ch, __nv_bfloat16* __restrict__ cl)
{
    __shared__ __align__(16) __half sQ[AQ * AROW];
    __shared__ __align__(16) __half sK[2][AKV * AROW];
    __shared__ __align__(16) __half sV[2][AKV * AROW];
    __shared__ int sM[2][AKV];

    int tid = threadIdx.x, wid = tid >> 5, lid = tid & 31;
    int qt = gridDim.x - 1 - blockIdx.x;    // heavy tiles first
    int h = blockIdx.y, b = blockIdx.z;
    int q0 = qt * AQ;
    int wm = wid * 16;

    uint32_t sQb = smem_to_u32(sQ);
    uint32_t sKb[2] = { smem_to_u32(sK[0]), smem_to_u32(sK[1]) };
    uint32_t sVb[2] = { smem_to_u32(sV[0]), smem_to_u32(sV[1]) };

    // ldmatrix lane patterns (same conventions as tc_gemm)
    int a_row = ((lid >> 3) & 1) * 8 + (lid & 7);
    int a_colh = (lid >> 4) * 8;
    int b_row = (lid >> 4) * 8 + (lid & 7);
    int b_colh = ((lid >> 3) & 1) * 8;
    // V (trans) lane pattern: row = kv within k16, col = dh within n16
    int v_row = ((lid >> 3) & 1) * 8 + (lid & 7);
    int v_colh = (lid >> 4) * 8;

    // ---- load Q tile (once) + K/V tile 0 ----
    {
        // Q: 64 rows x 128B = 512 chunks
        #pragma unroll
        for (int u = 0; u < 4; u++) {
            int cid = tid + u * 128;
            int r = cid >> 3, c = cid & 7;
            cp_async16(sQb + r * 144 + c * 16,
                       Qg + ((size_t)(b * SS + q0 + r)) * DD + h * DH + c * 8);
        }
        // K,V tile 0: 1024 chunks
        #pragma unroll
        for (int u = 0; u < 8; u++) {
            int cid = tid + u * 128;
            int kv = (cid < 512) ? 0 : 1;
            int rem = cid & 511;
            int r = rem >> 3, c = rem & 7;
            const __half* src = kv ? Vg : Kg;
            uint32_t dst = (kv ? sVb[0] : sKb[0]) + r * 144 + c * 16;
            cp_async16(dst, src + ((size_t)(b * SS + r)) * DD + h * DH + c * 8);
        }
        if (tid < AKV) sM[0][tid] = amask[b * SS + tid];
        CP_COMMIT();
    }

    int g = lid >> 2, t4i = lid & 3;
    int qg0 = q0 + wm + g;          // global q row (first of pair)
    int mq0 = amask[b * SS + qg0];
    int mq1 = amask[b * SS + qg0 + 8];

    float m0 = -1e30f, m1 = -1e30f, l0 = 0.0f, l1 = 0.0f;
    float ctx[8][4];
    #pragma unroll
    for (int nf = 0; nf < 8; nf++)
        #pragma unroll
        for (int j = 0; j < 4; j++) ctx[nf][j] = 0.0f;

    uint32_t qa[4][4];   // Q a-frags per dh k-group, loaded after first wait

    int ntiles = qt + 1;
    for (int t = 0; t < ntiles; t++) {
        int buf = t & 1;
        if (t + 1 < ntiles) {
            int nb = (t + 1) & 1;
            int k0n = (t + 1) * AKV;
            #pragma unroll
            for (int u = 0; u < 8; u++) {
                int cid = tid + u * 128;
                int kv = (cid < 512) ? 0 : 1;
                int rem = cid & 511;
                int r = rem >> 3, c = rem & 7;
                const __half* src = kv ? Vg : Kg;
                uint32_t dst = (kv ? sVb[nb] : sKb[nb]) + r * 144 + c * 16;
                cp_async16(dst, src + ((size_t)(b * SS + k0n + r)) * DD + h * DH + c * 8);
            }
            if (tid < AKV) sM[nb][tid] = amask[b * SS + k0n + tid];
            CP_COMMIT();
            CP_WAIT_1();
        } else {
            CP_WAIT_0();
        }
        __syncthreads();

        if (t == 0) {
            #pragma unroll
            for (int kg = 0; kg < 4; kg++) {
                uint32_t ra = sQb + (uint32_t)((wm + a_row) * 144 + (kg * 16 + a_colh) * 2);
                ldsm_x4(ra, qa[kg]);
            }
        }

        // ---- S = Q @ K^T ----
        float S[8][4];
        #pragma unroll
        for (int nf = 0; nf < 8; nf++)
            #pragma unroll
            for (int j = 0; j < 4; j++) S[nf][j] = 0.0f;

        #pragma unroll
        for (int kg = 0; kg < 4; kg++) {
            uint32_t kb[8][2];
            #pragma unroll
            for (int ng = 0; ng < 4; ng++) {
                uint32_t t4r[4];
                ldsm_x4(sKb[buf] + (uint32_t)((ng * 16 + b_row) * 144 + (kg * 16 + b_colh) * 2), t4r);
                kb[2*ng][0] = t4r[0]; kb[2*ng][1] = t4r[1];
                kb[2*ng+1][0] = t4r[2]; kb[2*ng+1][1] = t4r[3];
            }
            #pragma unroll
            for (int nf = 0; nf < 8; nf++)
                mma_fp16(S[nf], qa[kg], kb[nf]);
        }

        // ---- mask + online softmax ----
        int k0t = t * AKV;
        const float scale = 0.125f;
        float rm0 = -1e30f, rm1 = -1e30f;
        #pragma unroll
        for (int nf = 0; nf < 8; nf++) {
            int c0 = nf * 8 + 2 * t4i, c1 = c0 + 1;
            int km0 = sM[buf][c0], km1 = sM[buf][c1];
            int kn0 = k0t + c0, kn1 = k0t + c1;
            float s0 = S[nf][0] * scale, s1 = S[nf][1] * scale;
            float s2 = S[nf][2] * scale, s3 = S[nf][3] * scale;
            if (kn0 > qg0     || km0 == 0 || mq0 == 0) s0 = -1e30f;
            if (kn1 > qg0     || km1 == 0 || mq0 == 0) s1 = -1e30f;
            if (kn0 > qg0 + 8 || km0 == 0 || mq1 == 0) s2 = -1e30f;
            if (kn1 > qg0 + 8 || km1 == 0 || mq1 == 0) s3 = -1e30f;
            S[nf][0] = s0; S[nf][1] = s1; S[nf][2] = s2; S[nf][3] = s3;
            rm0 = fmaxf(rm0, fmaxf(s0, s1));
            rm1 = fmaxf(rm1, fmaxf(s2, s3));
        }
        rm0 = fmaxf(rm0, __shfl_xor_sync(0xffffffffu, rm0, 1));
        rm0 = fmaxf(rm0, __shfl_xor_sync(0xffffffffu, rm0, 2));
        rm1 = fmaxf(rm1, __shfl_xor_sync(0xffffffffu, rm1, 1));
        rm1 = fmaxf(rm1, __shfl_xor_sync(0xffffffffu, rm1, 2));
        float nm0 = fmaxf(m0, rm0), nm1 = fmaxf(m1, rm1);
        float corr0 = __expf(m0 - nm0), corr1 = __expf(m1 - nm1);
        m0 = nm0; m1 = nm1;
        float rs0 = 0.0f, rs1 = 0.0f;
        #pragma unroll
        for (int nf = 0; nf < 8; nf++) {
            float p0 = __expf(S[nf][0] - m0), p1 = __expf(S[nf][1] - m0);
            float p2 = __expf(S[nf][2] - m1), p3 = __expf(S[nf][3] - m1);
            S[nf][0] = p0; S[nf][1] = p1; S[nf][2] = p2; S[nf][3] = p3;
            rs0 += p0 + p1; rs1 += p2 + p3;
        }
        rs0 += __shfl_xor_sync(0xffffffffu, rs0, 1);
        rs0 += __shfl_xor_sync(0xffffffffu, rs0, 2);
        rs1 += __shfl_xor_sync(0xffffffffu, rs1, 1);
        rs1 += __shfl_xor_sync(0xffffffffu, rs1, 2);
        l0 = l0 * corr0 + rs0;
        l1 = l1 * corr1 + rs1;
        #pragma unroll
        for (int nf = 0; nf < 8; nf++) {
            ctx[nf][0] *= corr0; ctx[nf][1] *= corr0;
            ctx[nf][2] *= corr1; ctx[nf][3] *= corr1;
        }

        // ---- pack P (C-frag -> A-frag) ----
        uint32_t pa[4][4];
        #pragma unroll
        for (int kg = 0; kg < 4; kg++) {
            pa[kg][0] = pack_h2(S[2*kg][0],   S[2*kg][1]);
            pa[kg][1] = pack_h2(S[2*kg][2],   S[2*kg][3]);
            pa[kg][2] = pack_h2(S[2*kg+1][0], S[2*kg+1][1]);
            pa[kg][3] = pack_h2(S[2*kg+1][2], S[2*kg+1][3]);
        }

        // ---- ctx += P @ V ----
        #pragma unroll
        for (int kg = 0; kg < 4; kg++) {
            uint32_t vb[8][2];
            #pragma unroll
            for (int ng = 0; ng < 4; ng++) {
                uint32_t t4r[4];
                ldsm_x4_t(sVb[buf] + (uint32_t)((kg * 16 + v_row) * 144 + (ng * 16 + v_colh) * 2), t4r);
                vb[2*ng][0] = t4r[0]; vb[2*ng][1] = t4r[1];
                vb[2*ng+1][0] = t4r[2]; vb[2*ng+1][1] = t4r[3];
            }
            #pragma unroll
            for (int nf = 0; nf < 8; nf++)
                mma_fp16(ctx[nf], pa[kg], vb[nf]);
        }
        __syncthreads();
    }

    // ---- write ctx as split bf16 ----
    float inv0 = 1.0f / l0, inv1 = 1.0f / l1;
    #pragma unroll
    for (int nf = 0; nf < 8; nf++) {
        int col = nf * 8 + 2 * t4i;
        size_t o0 = ((size_t)(b * SS + qg0)) * DD + h * DH + col;
        size_t o1 = ((size_t)(b * SS + qg0 + 8)) * DD + h * DH + col;
        float d0 = ctx[nf][0] * inv0, d1 = ctx[nf][1] * inv0;
        float d2 = ctx[nf][2] * inv1, d3 = ctx[nf][3] * inv1;
        __nv_bfloat16 h0,h1,h2,h3,l0b,l1b,l2b,l3b;
        split_bf16(d0,h0,l0b); split_bf16(d1,h1,l1b);
        split_bf16(d2,h2,l2b); split_bf16(d3,h3,l3b);
        *(__nv_bfloat162*)(ch + o0) = __halves2bfloat162(h0, h1);
        *(__nv_bfloat162*)(cl + o0) = __halves2bfloat162(l0b, l1b);
        *(__nv_bfloat162*)(ch + o1) = __halves2bfloat162(h2, h3);
        *(__nv_bfloat162*)(cl + o1) = __halves2bfloat162(l2b, l3b);
    }
}

// ---------------- orchestration ----------------
extern "C" void kernel_launch(void* const* d_in, const int* in_sizes, int n_in,
                              void* d_out, int out_size)
{
    const float* x    = (const float*)d_in[0];
    const int*   am   = (const int*)  d_in[1];
    const float* ln1a = (const float*)d_in[2];
    const float* ln1b = (const float*)d_in[3];
    const float* ln2a = (const float*)d_in[4];
    const float* ln2b = (const float*)d_in[5];
    const float* Wq   = (const float*)d_in[6];
    const float* Wk   = (const float*)d_in[7];
    const float* Wv   = (const float*)d_in[8];
    const float* Wo   = (const float*)d_in[9];
    const float* W1   = (const float*)d_in[10];
    const float* b1   = (const float*)d_in[11];
    const float* W2   = (const float*)d_in[12];
    const float* b2   = (const float*)d_in[13];
    float* out = (float*)d_out;

    float *q, *k, *v, *x1;
    cudaGetSymbolAddress((void**)&q,  g_q);
    cudaGetSymbolAddress((void**)&k,  g_k);
    cudaGetSymbolAddress((void**)&v,  g_v);
    cudaGetSymbolAddress((void**)&x1, g_x1);

    __nv_bfloat16 *yh,*yl,*ch,*cl,*y2h,*y2l,*hh,*hl;
    __nv_bfloat16 *wqh,*wql,*wkh,*wkl,*wvh,*wvl,*woh,*wol,*w1h,*w1l,*w2h,*w2l;
    cudaGetSymbolAddress((void**)&yh,  g_yh);  cudaGetSymbolAddress((void**)&yl,  g_yl);
    cudaGetSymbolAddress((void**)&ch,  g_ch);  cudaGetSymbolAddress((void**)&cl,  g_cl);
    cudaGetSymbolAddress((void**)&y2h, g_y2h); cudaGetSymbolAddress((void**)&y2l, g_y2l);
    cudaGetSymbolAddress((void**)&hh,  g_hh);  cudaGetSymbolAddress((void**)&hl,  g_hl);
    cudaGetSymbolAddress((void**)&wqh, g_wqh); cudaGetSymbolAddress((void**)&wql, g_wql);
    cudaGetSymbolAddress((void**)&wkh, g_wkh); cudaGetSymbolAddress((void**)&wkl, g_wkl);
    cudaGetSymbolAddress((void**)&wvh, g_wvh); cudaGetSymbolAddress((void**)&wvl, g_wvl);
    cudaGetSymbolAddress((void**)&woh, g_woh); cudaGetSymbolAddress((void**)&wol, g_wol);
    cudaGetSymbolAddress((void**)&w1h, g_w1h); cudaGetSymbolAddress((void**)&w1l, g_w1l);
    cudaGetSymbolAddress((void**)&w2h, g_w2h); cudaGetSymbolAddress((void**)&w2l, g_w2l);

    cudaFuncSetAttribute(tc_gemm<0>, cudaFuncAttributeMaxDynamicSharedMemorySize, GEMM_DSMEM);
    cudaFuncSetAttribute(tc_gemm<1>, cudaFuncAttributeMaxDynamicSharedMemorySize, GEMM_DSMEM);
    cudaFuncSetAttribute(tc_gemm<2>, cudaFuncAttributeMaxDynamicSharedMemorySize, GEMM_DSMEM);
    cudaFuncSetAttribute(tc_gemm<3>, cudaFuncAttributeMaxDynamicSharedMemorySize, GEMM_DSMEM);
    cudaFuncSetAttribute(tc_gemm<4>, cudaFuncAttributeMaxDynamicSharedMemorySize, GEMM_DSMEM);

    dim3 gD(DD / BNT,  MTOT / BMT);   // (8, 64)
    dim3 gF(DFF / BNT, MTOT / BMT);   // (32, 64)

    // launch order chosen so ncu's "-s 5" slot lands on tc_gemm (gemmK)
    wsplit_kernel<<<dim3(DD/32,  DD/32),  256>>>(Wq, wqh, wql, DD,  DD);     // 0
    wsplit_kernel<<<dim3(DD/32,  DD/32),  256>>>(Wk, wkh, wkl, DD,  DD);     // 1
    wsplit_kernel<<<dim3(DD/32,  DD/32),  256>>>(Wv, wvh, wvl, DD,  DD);     // 2
    ln_kernel<<<MTOT, 256>>>(x, ln1a, ln1b, yh, yl);                         // 3
    tc_gemm<4><<<gD, 256, GEMM_DSMEM>>>(yh, yl, wqh, wql, nullptr, nullptr,  // 4
                                        nullptr, (__nv_bfloat16*)q, nullptr, MTOT, DD, DD);
    tc_gemm<4><<<gD, 256, GEMM_DSMEM>>>(yh, yl, wkh, wkl, nullptr, nullptr,  // 5 <- profiled
                                        nullptr, (__nv_bfloat16*)k, nullptr, MTOT, DD, DD);
    tc_gemm<4><<<gD, 256, GEMM_DSMEM>>>(yh, yl, wvh, wvl, nullptr, nullptr,  // 6
                                        nullptr, (__nv_bfloat16*)v, nullptr, MTOT, DD, DD);
    wsplit_kernel<<<dim3(DD/32,  DD/32),  256>>>(Wo, woh, wol, DD,  DD);     // 7
    attn_mma_kernel<<<dim3(SS / AQ, HH, BB), 128>>>(                         // 8
        (const __half*)q, (const __half*)k, (const __half*)v, am, ch, cl);
    tc_gemm<1><<<gD, 256, GEMM_DSMEM>>>(ch, cl, woh, wol, nullptr, x,        // 9
                                        x1, nullptr, nullptr, MTOT, DD, DD);
    ln_kernel<<<MTOT, 256>>>(x1, ln2a, ln2b, y2h, y2l);                      // 10
    wsplit_kernel<<<dim3(DFF/32, DD/32),  256>>>(W1, w1h, w1l, DD,  DFF);    // 11
    tc_gemm<2><<<gF, 256, GEMM_DSMEM>>>(y2h, y2l, w1h, w1l, b1, nullptr,     // 12
                                        nullptr, hh, hl, MTOT, DFF, DD);
    wsplit_kernel<<<dim3(DD/32,  DFF/32), 256>>>(W2, w2h, w2l, DFF, DD);     // 13
    tc_gemm<3><<<gD, 256, GEMM_DSMEM>>>(hh, hl, w2h, w2l, b2, x1,            // 14
                                        out, nullptr, nullptr, MTOT, DD, DFF);
}

// round 11
// speedup vs baseline: 4.2171x; 1.4148x over previous
#include <cuda_runtime.h>
#include <cuda_bf16.h>
#include <cuda_fp16.h>
#include <cstdint>
#include <math.h>

// ---------------- problem constants ----------------
#define BB   4
#define SS   2048
#define DD   1024
#define HH   16
#define DH   64
#define DFF  4096
#define MTOT (BB*SS)   // 8192 rows

// ---------------- scratch (device globals; no allocations allowed) ----------
__device__ float g_q [MTOT*DD];   // reused as fp16
__device__ float g_k [MTOT*DD];   // reused as fp16
__device__ float g_v [MTOT*DD];   // reused as fp16
__device__ float g_x1[MTOT*DD];

__device__ unsigned short g_yh [MTOT*DD];                       // fp16 y (LN1)
__device__ unsigned short g_ch [MTOT*DD],  g_cl [MTOT*DD];      // ctx bf16 hi/lo
__device__ unsigned short g_y2h[MTOT*DD];                       // fp16 y2 (LN2)
__device__ unsigned short g_hh [MTOT*DFF], g_hl [MTOT*DFF];     // gelu out bf16 hi/lo

__device__ unsigned short g_wqh[DD*DD];                         // fp16 Wq^T
__device__ unsigned short g_wkh[DD*DD];                         // fp16 Wk^T
__device__ unsigned short g_wvh[DD*DD];                         // fp16 Wv^T
__device__ unsigned short g_woh[DD*DD],  g_wol[DD*DD];          // bf16 Wo^T hi/lo
__device__ unsigned short g_w1h[DD*DFF];                        // fp16 W1^T
__device__ unsigned short g_w2h[DFF*DD], g_w2l[DFF*DD];         // bf16 W2^T hi/lo

// ---------------- PTX helpers (baseline sm_80+ features only) ----------------
__device__ __forceinline__ uint32_t smem_to_u32(const void* p) {
    uint32_t a;
    asm("{ .reg .u64 t; cvta.to.shared.u64 t, %1; cvt.u32.u64 %0, t; }" : "=r"(a) : "l"(p));
    return a;
}
__device__ __forceinline__ void cp_async16(uint32_t s, const void* g) {
    asm volatile("cp.async.cg.shared.global [%0], [%1], 16;" :: "r"(s), "l"(g) : "memory");
}
#define CP_COMMIT() asm volatile("cp.async.commit_group;" ::: "memory")
#define CP_WAIT_0() asm volatile("cp.async.wait_group 0;" ::: "memory")
#define CP_WAIT_1() asm volatile("cp.async.wait_group 1;" ::: "memory")

__device__ __forceinline__ void ldsm_x4(uint32_t addr, uint32_t r[4]) {
    asm volatile("ldmatrix.sync.aligned.m8n8.x4.shared.b16 {%0,%1,%2,%3}, [%4];"
                 : "=r"(r[0]), "=r"(r[1]), "=r"(r[2]), "=r"(r[3]) : "r"(addr));
}
__device__ __forceinline__ void ldsm_x4_t(uint32_t addr, uint32_t r[4]) {
    asm volatile("ldmatrix.sync.aligned.m8n8.x4.trans.shared.b16 {%0,%1,%2,%3}, [%4];"
                 : "=r"(r[0]), "=r"(r[1]), "=r"(r[2]), "=r"(r[3]) : "r"(addr));
}
__device__ __forceinline__ void mma_bf16(float d[4], const uint32_t a[4], const uint32_t b[2]) {
    asm volatile("mma.sync.aligned.m16n8k16.row.col.f32.bf16.bf16.f32 "
                 "{%0,%1,%2,%3}, {%4,%5,%6,%7}, {%8,%9}, {%0,%1,%2,%3};"
                 : "+f"(d[0]), "+f"(d[1]), "+f"(d[2]), "+f"(d[3])
                 : "r"(a[0]), "r"(a[1]), "r"(a[2]), "r"(a[3]), "r"(b[0]), "r"(b[1]));
}
__device__ __forceinline__ void mma_fp16(float d[4], const uint32_t a[4], const uint32_t b[2]) {
    asm volatile("mma.sync.aligned.m16n8k16.row.col.f32.f16.f16.f32 "
                 "{%0,%1,%2,%3}, {%4,%5,%6,%7}, {%8,%9}, {%0,%1,%2,%3};"
                 : "+f"(d[0]), "+f"(d[1]), "+f"(d[2]), "+f"(d[3])
                 : "r"(a[0]), "r"(a[1]), "r"(a[2]), "r"(a[3]), "r"(b[0]), "r"(b[1]));
}

__device__ __forceinline__ float gelu_exact(float v) {
    return 0.5f * v * (1.0f + erff(v * 0.70710678118654752f));
}
__device__ __forceinline__ void split_bf16(float v, __nv_bfloat16& h, __nv_bfloat16& l) {
    h = __float2bfloat16(v);
    l = __float2bfloat16(v - __bfloat162float(h));
}
__device__ __forceinline__ uint32_t pack_h2(float a, float b) {
    __half2 h = __floats2half2_rn(a, b);
    return *reinterpret_cast<uint32_t*>(&h);
}

// ---------------- LayerNorm -> fp16 ----------------
__global__ __launch_bounds__(256)
void ln_h_kernel(const float* __restrict__ x,
                 const float* __restrict__ alpha,
                 const float* __restrict__ beta,
                 __half* __restrict__ y)
{
    int row = blockIdx.x;
    int t = threadIdx.x;
    const float4* xr = (const float4*)(x + (size_t)row * DD);
    float4 v = xr[t];
    float s  = v.x + v.y + v.z + v.w;
    float sq = v.x*v.x + v.y*v.y + v.z*v.z + v.w*v.w;
    #pragma unroll
    for (int o = 16; o; o >>= 1) {
        s  += __shfl_xor_sync(0xffffffffu, s,  o);
        sq += __shfl_xor_sync(0xffffffffu, sq, o);
    }
    __shared__ float red[2][8];
    int w = t >> 5, lane = t & 31;
    if (lane == 0) { red[0][w] = s; red[1][w] = sq; }
    __syncthreads();
    if (t == 0) {
        float S = 0.f, Q = 0.f;
        #pragma unroll
        for (int i = 0; i < 8; i++) { S += red[0][i]; Q += red[1][i]; }
        float mean = S * (1.0f / DD);
        float var  = Q * (1.0f / DD) - mean * mean;
        red[0][0] = mean;
        red[1][0] = rsqrtf(var + 1e-5f);
    }
    __syncthreads();
    float mean = red[0][0], rstd = red[1][0];
    float4 a = ((const float4*)alpha)[t];
    float4 b = ((const float4*)beta)[t];
    float o0 = a.x * (v.x - mean) * rstd + b.x;
    float o1 = a.y * (v.y - mean) * rstd + b.y;
    float o2 = a.z * (v.z - mean) * rstd + b.z;
    float o3 = a.w * (v.w - mean) * rstd + b.w;
    size_t off = (size_t)row * DD + t * 4;
    *(__half2*)(y + off)     = __floats2half2_rn(o0, o1);
    *(__half2*)(y + off + 2) = __floats2half2_rn(o2, o3);
}

// ---------------- weight transpose: W[K,N] -> Wt[N,K] ----------------
__global__ __launch_bounds__(256)
void wsplit_kernel(const float* __restrict__ W,
                   __nv_bfloat16* __restrict__ Th,
                   __nv_bfloat16* __restrict__ Tl, int K, int N)
{
    __shared__ float t[32][33];
    int n0 = blockIdx.x * 32, k0 = blockIdx.y * 32;
    int tx = threadIdx.x & 31, ty = threadIdx.x >> 5;
    #pragma unroll
    for (int i = 0; i < 32; i += 8)
        t[ty + i][tx] = W[(size_t)(k0 + ty + i) * N + n0 + tx];
    __syncthreads();
    #pragma unroll
    for (int i = 0; i < 32; i += 8) {
        float v = t[tx][ty + i];
        __nv_bfloat16 h, l; split_bf16(v, h, l);
        size_t o = (size_t)(n0 + ty + i) * K + k0 + tx;
        Th[o] = h; Tl[o] = l;
    }
}

__global__ __launch_bounds__(256)
void wsplit_h_kernel(const float* __restrict__ W,
                     __half* __restrict__ T, int K, int N)
{
    __shared__ float t[32][33];
    int n0 = blockIdx.x * 32, k0 = blockIdx.y * 32;
    int tx = threadIdx.x & 31, ty = threadIdx.x >> 5;
    #pragma unroll
    for (int i = 0; i < 32; i += 8)
        t[ty + i][tx] = W[(size_t)(k0 + ty + i) * N + n0 + tx];
    __syncthreads();
    #pragma unroll
    for (int i = 0; i < 32; i += 8) {
        size_t o = (size_t)(n0 + ty + i) * K + k0 + tx;
        T[o] = __float2half_rn(t[tx][ty + i]);
    }
}

// ---------------- shared GEMM geometry ----------------
#define BMT 128
#define BNT 128
#define BKT32 32
#define ROWB 80
#define TILE_B (128 * ROWB)

// ============ 3-pass split-bf16 GEMM (precision path: Wo, W2) ============
// EPI 1: C fp32 = res + acc
// EPI 3: C fp32 = res + acc + bias
#define STAGE_B (4 * TILE_B)
#define GEMM_DSMEM (2 * STAGE_B + 128)

__device__ __forceinline__ void load_stage(
    uint32_t sbase, const __nv_bfloat16* Ah, const __nv_bfloat16* Al,
    const __nv_bfloat16* Bh, const __nv_bfloat16* Bl,
    int m0, int n0, int k0, int K, int tid)
{
    #pragma unroll
    for (int u = 0; u < 8; u++) {
        int cid = tid + u * 256;
        int tile = cid >> 9;
        int rem = cid & 511;
        int r = rem >> 2, c = rem & 3;
        const __nv_bfloat16* src = (tile == 0) ? Ah : (tile == 1) ? Al : (tile == 2) ? Bh : Bl;
        int row = ((tile < 2) ? m0 : n0) + r;
        const __nv_bfloat16* g = src + (size_t)row * K + k0 + c * 8;
        uint32_t s = sbase + tile * TILE_B + r * ROWB + c * 16;
        cp_async16(s, g);
    }
}

template<int EPI>
__global__ __launch_bounds__(256)
void tc_gemm(const __nv_bfloat16* __restrict__ Ah, const __nv_bfloat16* __restrict__ Al,
             const __nv_bfloat16* __restrict__ Bh, const __nv_bfloat16* __restrict__ Bl,
             const float* __restrict__ bias, const float* __restrict__ res,
             float* __restrict__ C, int M, int N, int K)
{
    extern __shared__ __align__(128) char dsm[];
    uint32_t sb = smem_to_u32(dsm);

    int tid = threadIdx.x, wid = tid >> 5, lid = tid & 31;
    int n0 = blockIdx.x * BNT, m0 = blockIdx.y * BMT;
    int wm = (wid >> 1) * 32;
    int wn = (wid & 1) * 64;

    float acc[2][8][4];
    #pragma unroll
    for (int mt = 0; mt < 2; mt++)
        #pragma unroll
        for (int nt = 0; nt < 8; nt++)
            #pragma unroll
            for (int j = 0; j < 4; j++) acc[mt][nt][j] = 0.0f;

    int a_row = ((lid >> 3) & 1) * 8 + (lid & 7);
    int a_colh = (lid >> 4) * 8;
    int b_row = (lid >> 4) * 8 + (lid & 7);
    int b_colh = ((lid >> 3) & 1) * 8;

    int nch = K / BKT32;

    load_stage(sb, Ah, Al, Bh, Bl, m0, n0, 0, K, tid);
    CP_COMMIT();

    for (int i = 0; i < nch; i++) {
        uint32_t st = sb + (uint32_t)(i & 1) * STAGE_B;
        if (i + 1 < nch) {
            load_stage(sb + (uint32_t)((i + 1) & 1) * STAGE_B,
                       Ah, Al, Bh, Bl, m0, n0, (i + 1) * BKT32, K, tid);
            CP_COMMIT();
            CP_WAIT_1();
        } else {
            CP_WAIT_0();
        }
        __syncthreads();

        uint32_t tAh = st;
        uint32_t tAl = st + TILE_B;
        uint32_t tBh = st + 2 * TILE_B;
        uint32_t tBl = st + 3 * TILE_B;

        #pragma unroll
        for (int ks = 0; ks < 2; ks++) {
            uint32_t ah[2][4], al[2][4], bh[8][2], bl[8][2];
            #pragma unroll
            for (int mt = 0; mt < 2; mt++) {
                uint32_t ra = (uint32_t)((wm + mt * 16 + a_row) * ROWB + (ks * 16 + a_colh) * 2);
                ldsm_x4(tAh + ra, ah[mt]);
                ldsm_x4(tAl + ra, al[mt]);
            }
            #pragma unroll
            for (int ng = 0; ng < 4; ng++) {
                uint32_t rb = (uint32_t)((wn + ng * 16 + b_row) * ROWB + (ks * 16 + b_colh) * 2);
                uint32_t t4[4];
                ldsm_x4(tBh + rb, t4);
                bh[2*ng][0] = t4[0]; bh[2*ng][1] = t4[1];
                bh[2*ng+1][0] = t4[2]; bh[2*ng+1][1] = t4[3];
                ldsm_x4(tBl + rb, t4);
                bl[2*ng][0] = t4[0]; bl[2*ng][1] = t4[1];
                bl[2*ng+1][0] = t4[2]; bl[2*ng+1][1] = t4[3];
            }
            #pragma unroll
            for (int mt = 0; mt < 2; mt++)
                #pragma unroll
                for (int nt = 0; nt < 8; nt++) {
                    mma_bf16(acc[mt][nt], ah[mt], bh[nt]);
                    mma_bf16(acc[mt][nt], ah[mt], bl[nt]);
                    mma_bf16(acc[mt][nt], al[mt], bh[nt]);
                }
        }
        __syncthreads();
    }

    int g = lid >> 2, t4i = lid & 3;
    #pragma unroll
    for (int mt = 0; mt < 2; mt++) {
        #pragma unroll
        for (int nt = 0; nt < 8; nt++) {
            int row0 = m0 + wm + mt * 16 + g;
            int row1 = row0 + 8;
            int col  = n0 + wn + nt * 8 + 2 * t4i;
            float d0 = acc[mt][nt][0], d1 = acc[mt][nt][1];
            float d2 = acc[mt][nt][2], d3 = acc[mt][nt][3];
            if (EPI == 3) {
                float2 bv = *(const float2*)(bias + col);
                d0 += bv.x; d1 += bv.y; d2 += bv.x; d3 += bv.y;
            }
            float2 r0 = *(const float2*)(res + (size_t)row0 * N + col);
            float2 r1 = *(const float2*)(res + (size_t)row1 * N + col);
            d0 += r0.x; d1 += r0.y; d2 += r1.x; d3 += r1.y;
            *(float2*)(C + (size_t)row0 * N + col) = make_float2(d0, d1);
            *(float2*)(C + (size_t)row1 * N + col) = make_float2(d2, d3);
        }
    }
}

// ============ single-pass fp16 GEMM (throughput path: QKV, W1) ============
// EPI 4: Hout fp16 = acc
// EPI 2: Ch/Cl bf16 split of gelu(acc + bias)
#define STAGE_H (2 * TILE_B)
#define GEMM_H_DSMEM (2 * STAGE_H + 128)

__device__ __forceinline__ void load_stage_h(
    uint32_t sbase, const __half* A, const __half* B,
    int m0, int n0, int k0, int K, int tid)
{
    #pragma unroll
    for (int u = 0; u < 4; u++) {
        int cid = tid + u * 256;          // 0..1023
        int tile = cid >> 9;              // 0..1
        int rem = cid & 511;
        int r = rem >> 2, c = rem & 3;
        const __half* src = tile ? B : A;
        int row = (tile ? n0 : m0) + r;
        const __half* g = src + (size_t)row * K + k0 + c * 8;
        uint32_t s = sbase + tile * TILE_B + r * ROWB + c * 16;
        cp_async16(s, g);
    }
}

template<int EPI>
__global__ __launch_bounds__(256)
void tc_gemm_h(const __half* __restrict__ A, const __half* __restrict__ B,
               const float* __restrict__ bias,
               __half* __restrict__ Hout,
               __nv_bfloat16* __restrict__ Ch, __nv_bfloat16* __restrict__ Cl,
               int M, int N, int K)
{
    extern __shared__ __align__(128) char dsm[];
    uint32_t sb = smem_to_u32(dsm);

    int tid = threadIdx.x, wid = tid >> 5, lid = tid & 31;
    int n0 = blockIdx.x * BNT, m0 = blockIdx.y * BMT;
    int wm = (wid >> 1) * 32;
    int wn = (wid & 1) * 64;

    float acc[2][8][4];
    #pragma unroll
    for (int mt = 0; mt < 2; mt++)
        #pragma unroll
        for (int nt = 0; nt < 8; nt++)
            #pragma unroll
            for (int j = 0; j < 4; j++) acc[mt][nt][j] = 0.0f;

    int a_row = ((lid >> 3) & 1) * 8 + (lid & 7);
    int a_colh = (lid >> 4) * 8;
    int b_row = (lid >> 4) * 8 + (lid & 7);
    int b_colh = ((lid >> 3) & 1) * 8;

    int nch = K / BKT32;

    load_stage_h(sb, A, B, m0, n0, 0, K, tid);
    CP_COMMIT();

    for (int i = 0; i < nch; i++) {
        uint32_t st = sb + (uint32_t)(i & 1) * STAGE_H;
        if (i + 1 < nch) {
            load_stage_h(sb + (uint32_t)((i + 1) & 1) * STAGE_H,
                         A, B, m0, n0, (i + 1) * BKT32, K, tid);
            CP_COMMIT();
            CP_WAIT_1();
        } else {
            CP_WAIT_0();
        }
        __syncthreads();

        uint32_t tA = st;
        uint32_t tB = st + TILE_B;

        #pragma unroll
        for (int ks = 0; ks < 2; ks++) {
            uint32_t ah[2][4], bh[8][2];
            #pragma unroll
            for (int mt = 0; mt < 2; mt++) {
                uint32_t ra = (uint32_t)((wm + mt * 16 + a_row) * ROWB + (ks * 16 + a_colh) * 2);
                ldsm_x4(tA + ra, ah[mt]);
            }
            #pragma unroll
            for (int ng = 0; ng < 4; ng++) {
                uint32_t rb = (uint32_t)((wn + ng * 16 + b_row) * ROWB + (ks * 16 + b_colh) * 2);
                uint32_t t4[4];
                ldsm_x4(tB + rb, t4);
                bh[2*ng][0] = t4[0]; bh[2*ng][1] = t4[1];
                bh[2*ng+1][0] = t4[2]; bh[2*ng+1][1] = t4[3];
            }
            #pragma unroll
            for (int mt = 0; mt < 2; mt++)
                #pragma unroll
                for (int nt = 0; nt < 8; nt++)
                    mma_fp16(acc[mt][nt], ah[mt], bh[nt]);
        }
        __syncthreads();
    }

    int g = lid >> 2, t4i = lid & 3;
    #pragma unroll
    for (int mt = 0; mt < 2; mt++) {
        #pragma unroll
        for (int nt = 0; nt < 8; nt++) {
            int row0 = m0 + wm + mt * 16 + g;
            int row1 = row0 + 8;
            int col  = n0 + wn + nt * 8 + 2 * t4i;
            float d0 = acc[mt][nt][0], d1 = acc[mt][nt][1];
            float d2 = acc[mt][nt][2], d3 = acc[mt][nt][3];
            if (EPI == 2) {
                float2 bv = *(const float2*)(bias + col);
                d0 = gelu_exact(d0 + bv.x); d1 = gelu_exact(d1 + bv.y);
                d2 = gelu_exact(d2 + bv.x); d3 = gelu_exact(d3 + bv.y);
                __nv_bfloat16 h0,h1,h2,h3,l0,l1,l2,l3;
                split_bf16(d0,h0,l0); split_bf16(d1,h1,l1);
                split_bf16(d2,h2,l2); split_bf16(d3,h3,l3);
                *(__nv_bfloat162*)(Ch + (size_t)row0 * N + col) = __halves2bfloat162(h0, h1);
                *(__nv_bfloat162*)(Cl + (size_t)row0 * N + col) = __halves2bfloat162(l0, l1);
                *(__nv_bfloat162*)(Ch + (size_t)row1 * N + col) = __halves2bfloat162(h2, h3);
                *(__nv_bfloat162*)(Cl + (size_t)row1 * N + col) = __halves2bfloat162(l2, l3);
            } else {  // EPI == 4
                *(__half2*)(Hout + (size_t)row0 * N + col) = __floats2half2_rn(d0, d1);
                *(__half2*)(Hout + (size_t)row1 * N + col) = __floats2half2_rn(d2, d3);
            }
        }
    }
}

// ---------------- fp16 mma.sync flash attention (unchanged) ----------------
#define AQ   64
#define AKV  64

__global__ __launch_bounds__(128)
void attn_mma_kernel(const __half* __restrict__ Qg, const __half* __restrict__ Kg,
                     const __half* __restrict__ Vg, const int* __restrict__ amask,
                     __nv_bfloat16* __restrict__ ch, __nv_bfloat16* __restrict__ cl)
{
    __shared__ __align__(16) __half sQ[AQ * 72];
    __shared__ __align__(16) __half sK[2][AKV * 72];
    __shared__ __align__(16) __half sV[2][AKV * 72];
    __shared__ int sM[2][AKV];

    int tid = threadIdx.x, wid = tid >> 5, lid = tid & 31;
    int qt = gridDim.x - 1 - blockIdx.x;
    int h = blockIdx.y, b = blockIdx.z;
    int q0 = qt * AQ;
    int wm = wid * 16;

    uint32_t sQb = smem_to_u32(sQ);
    uint32_t sKb[2] = { smem_to_u32(sK[0]), smem_to_u32(sK[1]) };
    uint32_t sVb[2] = { smem_to_u32(sV[0]), smem_to_u32(sV[1]) };

    int a_row = ((lid >> 3) & 1) * 8 + (lid & 7);
    int a_colh = (lid >> 4) * 8;
    int b_row = (lid >> 4) * 8 + (lid & 7);
    int b_colh = ((lid >> 3) & 1) * 8;
    int v_row = ((lid >> 3) & 1) * 8 + (lid & 7);
    int v_colh = (lid >> 4) * 8;

    {
        #pragma unroll
        for (int u = 0; u < 4; u++) {
            int cid = tid + u * 128;
            int r = cid >> 3, c = cid & 7;
            cp_async16(sQb + r * 144 + c * 16,
                       Qg + ((size_t)(b * SS + q0 + r)) * DD + h * DH + c * 8);
        }
        #pragma unroll
        for (int u = 0; u < 8; u++) {
            int cid = tid + u * 128;
            int kv = (cid < 512) ? 0 : 1;
            int rem = cid & 511;
            int r = rem >> 3, c = rem & 7;
            const __half* src = kv ? Vg : Kg;
            uint32_t dst = (kv ? sVb[0] : sKb[0]) + r * 144 + c * 16;
            cp_async16(dst, src + ((size_t)(b * SS + r)) * DD + h * DH + c * 8);
        }
        if (tid < AKV) sM[0][tid] = amask[b * SS + tid];
        CP_COMMIT();
    }

    int g = lid >> 2, t4i = lid & 3;
    int qg0 = q0 + wm + g;
    int mq0 = amask[b * SS + qg0];
    int mq1 = amask[b * SS + qg0 + 8];

    float m0 = -1e30f, m1 = -1e30f, l0 = 0.0f, l1 = 0.0f;
    float ctx[8][4];
    #pragma unroll
    for (int nf = 0; nf < 8; nf++)
        #pragma unroll
        for (int j = 0; j < 4; j++) ctx[nf][j] = 0.0f;

    uint32_t qa[4][4];

    int ntiles = qt + 1;
    for (int t = 0; t < ntiles; t++) {
        int buf = t & 1;
        if (t + 1 < ntiles) {
            int nb = (t + 1) & 1;
            int k0n = (t + 1) * AKV;
            #pragma unroll
            for (int u = 0; u < 8; u++) {
                int cid = tid + u * 128;
                int kv = (cid < 512) ? 0 : 1;
                int rem = cid & 511;
                int r = rem >> 3, c = rem & 7;
                const __half* src = kv ? Vg : Kg;
                uint32_t dst = (kv ? sVb[nb] : sKb[nb]) + r * 144 + c * 16;
                cp_async16(dst, src + ((size_t)(b * SS + k0n + r)) * DD + h * DH + c * 8);
            }
            if (tid < AKV) sM[nb][tid] = amask[b * SS + k0n + tid];
            CP_COMMIT();
            CP_WAIT_1();
        } else {
            CP_WAIT_0();
        }
        __syncthreads();

        if (t == 0) {
            #pragma unroll
            for (int kg = 0; kg < 4; kg++) {
                uint32_t ra = sQb + (uint32_t)((wm + a_row) * 144 + (kg * 16 + a_colh) * 2);
                ldsm_x4(ra, qa[kg]);
            }
        }

        float S[8][4];
        #pragma unroll
        for (int nf = 0; nf < 8; nf++)
            #pragma unroll
            for (int j = 0; j < 4; j++) S[nf][j] = 0.0f;

        #pragma unroll
        for (int kg = 0; kg < 4; kg++) {
            uint32_t kb[8][2];
            #pragma unroll
            for (int ng = 0; ng < 4; ng++) {
                uint32_t t4r[4];
                ldsm_x4(sKb[buf] + (uint32_t)((ng * 16 + b_row) * 144 + (kg * 16 + b_colh) * 2), t4r);
                kb[2*ng][0] = t4r[0]; kb[2*ng][1] = t4r[1];
                kb[2*ng+1][0] = t4r[2]; kb[2*ng+1][1] = t4r[3];
            }
            #pragma unroll
            for (int nf = 0; nf < 8; nf++)
                mma_fp16(S[nf], qa[kg], kb[nf]);
        }

        int k0t = t * AKV;
        const float scale = 0.125f;
        float rm0 = -1e30f, rm1 = -1e30f;
        #pragma unroll
        for (int nf = 0; nf < 8; nf++) {
            int c0 = nf * 8 + 2 * t4i, c1 = c0 + 1;
            int km0 = sM[buf][c0], km1 = sM[buf][c1];
            int kn0 = k0t + c0, kn1 = k0t + c1;
            float s0 = S[nf][0] * scale, s1 = S[nf][1] * scale;
            float s2 = S[nf][2] * scale, s3 = S[nf][3] * scale;
            if (kn0 > qg0     || km0 == 0 || mq0 == 0) s0 = -1e30f;
            if (kn1 > qg0     || km1 == 0 || mq0 == 0) s1 = -1e30f;
            if (kn0 > qg0 + 8 || km0 == 0 || mq1 == 0) s2 = -1e30f;
            if (kn1 > qg0 + 8 || km1 == 0 || mq1 == 0) s3 = -1e30f;
            S[nf][0] = s0; S[nf][1] = s1; S[nf][2] = s2; S[nf][3] = s3;
            rm0 = fmaxf(rm0, fmaxf(s0, s1));
            rm1 = fmaxf(rm1, fmaxf(s2, s3));
        }
        rm0 = fmaxf(rm0, __shfl_xor_sync(0xffffffffu, rm0, 1));
        rm0 = fmaxf(rm0, __shfl_xor_sync(0xffffffffu, rm0, 2));
        rm1 = fmaxf(rm1, __shfl_xor_sync(0xffffffffu, rm1, 1));
        rm1 = fmaxf(rm1, __shfl_xor_sync(0xffffffffu, rm1, 2));
        float nm0 = fmaxf(m0, rm0), nm1 = fmaxf(m1, rm1);
        float corr0 = __expf(m0 - nm0), corr1 = __expf(m1 - nm1);
        m0 = nm0; m1 = nm1;
        float rs0 = 0.0f, rs1 = 0.0f;
        #pragma unroll
        for (int nf = 0; nf < 8; nf++) {
            float p0 = __expf(S[nf][0] - m0), p1 = __expf(S[nf][1] - m0);
            float p2 = __expf(S[nf][2] - m1), p3 = __expf(S[nf][3] - m1);
            S[nf][0] = p0; S[nf][1] = p1; S[nf][2] = p2; S[nf][3] = p3;
            rs0 += p0 + p1; rs1 += p2 + p3;
        }
        rs0 += __shfl_xor_sync(0xffffffffu, rs0, 1);
        rs0 += __shfl_xor_sync(0xffffffffu, rs0, 2);
        rs1 += __shfl_xor_sync(0xffffffffu, rs1, 1);
        rs1 += __shfl_xor_sync(0xffffffffu, rs1, 2);
        l0 = l0 * corr0 + rs0;
        l1 = l1 * corr1 + rs1;
        #pragma unroll
        for (int nf = 0; nf < 8; nf++) {
            ctx[nf][0] *= corr0; ctx[nf][1] *= corr0;
            ctx[nf][2] *= corr1; ctx[nf][3] *= corr1;
        }

        uint32_t pa[4][4];
        #pragma unroll
        for (int kg = 0; kg < 4; kg++) {
            pa[kg][0] = pack_h2(S[2*kg][0],   S[2*kg][1]);
            pa[kg][1] = pack_h2(S[2*kg][2],   S[2*kg][3]);
            pa[kg][2] = pack_h2(S[2*kg+1][0], S[2*kg+1][1]);
            pa[kg][3] = pack_h2(S[2*kg+1][2], S[2*kg+1][3]);
        }

        #pragma unroll
        for (int kg = 0; kg < 4; kg++) {
            uint32_t vb[8][2];
            #pragma unroll
            for (int ng = 0; ng < 4; ng++) {
                uint32_t t4r[4];
                ldsm_x4_t(sVb[buf] + (uint32_t)((kg * 16 + v_row) * 144 + (ng * 16 + v_colh) * 2), t4r);
                vb[2*ng][0] = t4r[0]; vb[2*ng][1] = t4r[1];
                vb[2*ng+1][0] = t4r[2]; vb[2*ng+1][1] = t4r[3];
            }
            #pragma unroll
            for (int nf = 0; nf < 8; nf++)
                mma_fp16(ctx[nf], pa[kg], vb[nf]);
        }
        __syncthreads();
    }

    float inv0 = 1.0f / l0, inv1 = 1.0f / l1;
    #pragma unroll
    for (int nf = 0; nf < 8; nf++) {
        int col = nf * 8 + 2 * t4i;
        size_t o0 = ((size_t)(b * SS + qg0)) * DD + h * DH + col;
        size_t o1 = ((size_t)(b * SS + qg0 + 8)) * DD + h * DH + col;
        float d0 = ctx[nf][0] * inv0, d1 = ctx[nf][1] * inv0;
        float d2 = ctx[nf][2] * inv1, d3 = ctx[nf][3] * inv1;
        __nv_bfloat16 h0,h1,h2,h3,l0b,l1b,l2b,l3b;
        split_bf16(d0,h0,l0b); split_bf16(d1,h1,l1b);
        split_bf16(d2,h2,l2b); split_bf16(d3,h3,l3b);
        *(__nv_bfloat162*)(ch + o0) = __halves2bfloat162(h0, h1);
        *(__nv_bfloat162*)(cl + o0) = __halves2bfloat162(l0b, l1b);
        *(__nv_bfloat162*)(ch + o1) = __halves2bfloat162(h2, h3);
        *(__nv_bfloat162*)(cl + o1) = __halves2bfloat162(l2b, l3b);
    }
}

// ---------------- orchestration ----------------
extern "C" void kernel_launch(void* const* d_in, const int* in_sizes, int n_in,
                              void* d_out, int out_size)
{
    const float* x    = (const float*)d_in[0];
    const int*   am   = (const int*)  d_in[1];
    const float* ln1a = (const float*)d_in[2];
    const float* ln1b = (const float*)d_in[3];
    const float* ln2a = (const float*)d_in[4];
    const float* ln2b = (const float*)d_in[5];
    const float* Wq   = (const float*)d_in[6];
    const float* Wk   = (const float*)d_in[7];
    const float* Wv   = (const float*)d_in[8];
    const float* Wo   = (const float*)d_in[9];
    const float* W1   = (const float*)d_in[10];
    const float* b1   = (const float*)d_in[11];
    const float* W2   = (const float*)d_in[12];
    const float* b2   = (const float*)d_in[13];
    float* out = (float*)d_out;

    float *qf, *kf, *vf, *x1;
    cudaGetSymbolAddress((void**)&qf, g_q);
    cudaGetSymbolAddress((void**)&kf, g_k);
    cudaGetSymbolAddress((void**)&vf, g_v);
    cudaGetSymbolAddress((void**)&x1, g_x1);
    __half *q = (__half*)qf, *k = (__half*)kf, *v = (__half*)vf;

    __half *y, *y2, *whq, *whk, *whv, *wh1;
    __nv_bfloat16 *ch, *cl, *hh, *hl, *woh, *wol, *w2h, *w2l;
    cudaGetSymbolAddress((void**)&y,   g_yh);
    cudaGetSymbolAddress((void**)&y2,  g_y2h);
    cudaGetSymbolAddress((void**)&whq, g_wqh);
    cudaGetSymbolAddress((void**)&whk, g_wkh);
    cudaGetSymbolAddress((void**)&whv, g_wvh);
    cudaGetSymbolAddress((void**)&wh1, g_w1h);
    cudaGetSymbolAddress((void**)&ch,  g_ch);
    cudaGetSymbolAddress((void**)&cl,  g_cl);
    cudaGetSymbolAddress((void**)&hh,  g_hh);
    cudaGetSymbolAddress((void**)&hl,  g_hl);
    cudaGetSymbolAddress((void**)&woh, g_woh);
    cudaGetSymbolAddress((void**)&wol, g_wol);
    cudaGetSymbolAddress((void**)&w2h, g_w2h);
    cudaGetSymbolAddress((void**)&w2l, g_w2l);

    cudaFuncSetAttribute(tc_gemm<1>,   cudaFuncAttributeMaxDynamicSharedMemorySize, GEMM_DSMEM);
    cudaFuncSetAttribute(tc_gemm<3>,   cudaFuncAttributeMaxDynamicSharedMemorySize, GEMM_DSMEM);
    cudaFuncSetAttribute(tc_gemm_h<2>, cudaFuncAttributeMaxDynamicSharedMemorySize, GEMM_H_DSMEM);
    cudaFuncSetAttribute(tc_gemm_h<4>, cudaFuncAttributeMaxDynamicSharedMemorySize, GEMM_H_DSMEM);

    dim3 gD(DD / BNT,  MTOT / BMT);   // (8, 64)
    dim3 gF(DFF / BNT, MTOT / BMT);   // (32, 64)

    // order: 2 hidden harness launches precede; my idx 3 == global slot 5 (profiled)
    wsplit_h_kernel<<<dim3(DD/32, DD/32), 256>>>(Wq, whq, DD, DD);              // 0
    wsplit_h_kernel<<<dim3(DD/32, DD/32), 256>>>(Wk, whk, DD, DD);              // 1
    ln_h_kernel<<<MTOT, 256>>>(x, ln1a, ln1b, y);                               // 2
    tc_gemm_h<4><<<gD, 256, GEMM_H_DSMEM>>>(y, whq, nullptr, q,                 // 3 <- profiled
                                            nullptr, nullptr, MTOT, DD, DD);
    wsplit_h_kernel<<<dim3(DD/32, DD/32), 256>>>(Wv, whv, DD, DD);              // 4
    tc_gemm_h<4><<<gD, 256, GEMM_H_DSMEM>>>(y, whk, nullptr, k,                 // 5
                                            nullptr, nullptr, MTOT, DD, DD);
    tc_gemm_h<4><<<gD, 256, GEMM_H_DSMEM>>>(y, whv, nullptr, v,                 // 6
                                            nullptr, nullptr, MTOT, DD, DD);
    wsplit_kernel<<<dim3(DD/32, DD/32), 256>>>(Wo, woh, wol, DD, DD);           // 7
    attn_mma_kernel<<<dim3(SS / AQ, HH, BB), 128>>>(q, k, v, am, ch, cl);       // 8
    tc_gemm<1><<<gD, 256, GEMM_DSMEM>>>(ch, cl, woh, wol, nullptr, x,           // 9
                                        x1, MTOT, DD, DD);
    ln_h_kernel<<<MTOT, 256>>>(x1, ln2a, ln2b, y2);                             // 10
    wsplit_h_kernel<<<dim3(DFF/32, DD/32), 256>>>(W1, wh1, DD, DFF);            // 11
    tc_gemm_h<2><<<gF, 256, GEMM_H_DSMEM>>>(y2, wh1, b1, nullptr,               // 12
                                            hh, hl, MTOT, DFF, DD);
    wsplit_kernel<<<dim3(DD/32, DFF/32), 256>>>(W2, w2h, w2l, DFF, DD);         // 13
    tc_gemm<3><<<gD, 256, GEMM_DSMEM>>>(hh, hl, w2h, w2l, b2, x1,               // 14
                                        out, MTOT, DD, DFF);
}